// round 8
// baseline (speedup 1.0000x reference)
#include <cuda_runtime.h>
#include <cuda_bf16.h>
#include <math.h>
#include <stdint.h>

typedef __nv_bfloat16 bf16;

// ---------------------------------------------------------------------------
// Problem constants
// ---------------------------------------------------------------------------
#define B_    2
#define S_    2048
#define D_    1024
#define H_    16
#define DH_   64
#define M_TOT (B_ * S_)      // 4096
#define QKV_N (3 * D_)       // 3072
#define K_    1024
#define SCALE 0.125f
#define INV254 (1.0f / 254.0f)

// ---------------------------------------------------------------------------
// Scratch (__device__ globals)
// ---------------------------------------------------------------------------
__device__ int8_t g_xd0[M_TOT * K_],  g_xd1[M_TOT * K_];   float __device__ g_xs[M_TOT];
__device__ int8_t g_wqd0[QKV_N * K_], g_wqd1[QKV_N * K_];  float __device__ g_wqs[QKV_N];
__device__ int8_t g_wod0[D_ * K_],    g_wod1[D_ * K_];     float __device__ g_wos[D_];
__device__ int8_t g_ad0[M_TOT * K_],  g_ad1[M_TOT * K_];   float __device__ g_as[M_TOT];
__device__ bf16 g_qhi[M_TOT * QKV_N], g_qlo[M_TOT * QKV_N];  // qkv bf16 hi/lo
__device__ bf16 g_ahi[M_TOT * D_],    g_alo[M_TOT * D_];     // attn out bf16 hi/lo

// ---------------------------------------------------------------------------
// Helpers
// ---------------------------------------------------------------------------
__device__ __forceinline__ uint32_t sptr(const void* p) {
    return (uint32_t)__cvta_generic_to_shared(p);
}
__device__ __forceinline__ void cp16(uint32_t d, const void* s) {
    asm volatile("cp.async.cg.shared.global [%0], [%1], 16;" :: "r"(d), "l"(s));
}
#define CP_COMMIT() asm volatile("cp.async.commit_group;" ::: "memory")
#define CP_WAIT(n)  asm volatile("cp.async.wait_group %0;" :: "n"(n) : "memory")

__device__ __forceinline__ uint32_t sw128(uint32_t o) {   // Swizzle<3,4,3>
    return o ^ ((o >> 3) & 0x70);
}
__device__ __forceinline__ void ldsm4(uint32_t a, uint32_t r[4]) {
    asm volatile("ldmatrix.sync.aligned.m8n8.x4.shared.b16 {%0,%1,%2,%3}, [%4];"
                 : "=r"(r[0]), "=r"(r[1]), "=r"(r[2]), "=r"(r[3]) : "r"(a));
}
__device__ __forceinline__ void ldsm4t(uint32_t a, uint32_t r[4]) {
    asm volatile("ldmatrix.sync.aligned.m8n8.x4.trans.shared.b16 {%0,%1,%2,%3}, [%4];"
                 : "=r"(r[0]), "=r"(r[1]), "=r"(r[2]), "=r"(r[3]) : "r"(a));
}
__device__ __forceinline__ void mma_bf16(float c[4], const uint32_t a[4],
                                         uint32_t b0, uint32_t b1) {
    asm volatile(
        "mma.sync.aligned.m16n8k16.row.col.f32.bf16.bf16.f32 "
        "{%0,%1,%2,%3}, {%4,%5,%6,%7}, {%8,%9}, {%0,%1,%2,%3};"
        : "+f"(c[0]), "+f"(c[1]), "+f"(c[2]), "+f"(c[3])
        : "r"(a[0]), "r"(a[1]), "r"(a[2]), "r"(a[3]), "r"(b0), "r"(b1));
}
__device__ __forceinline__ void imma(int c[4], const uint32_t a[4],
                                     uint32_t b0, uint32_t b1) {
    asm volatile(
        "mma.sync.aligned.m16n8k32.row.col.s32.s8.s8.s32 "
        "{%0,%1,%2,%3}, {%4,%5,%6,%7}, {%8,%9}, {%0,%1,%2,%3};"
        : "+r"(c[0]), "+r"(c[1]), "+r"(c[2]), "+r"(c[3])
        : "r"(a[0]), "r"(a[1]), "r"(a[2]), "r"(a[3]), "r"(b0), "r"(b1));
}
__device__ __forceinline__ void split_pack(float a, float b, uint32_t& hi, uint32_t& lo) {
    __nv_bfloat162 hp = __floats2bfloat162_rn(a, b);
    float ra = a - __bfloat162float(hp.x);
    float rb = b - __bfloat162float(hp.y);
    __nv_bfloat162 lp = __floats2bfloat162_rn(ra, rb);
    hi = *(uint32_t*)&hp;
    lo = *(uint32_t*)&lp;
}

// ---------------------------------------------------------------------------
// Row quantization: v = s * (d0 + d1/254), per-1024-row scale.
// ---------------------------------------------------------------------------
__device__ __forceinline__ void quant_store(float f[4], uint32_t& p0, uint32_t& p1) {
    p0 = 0; p1 = 0;
    #pragma unroll
    for (int j = 0; j < 4; j++) {
        int a = __float2int_rn(f[j]);
        int b = __float2int_rn((f[j] - (float)a) * 254.0f);
        p0 |= ((uint32_t)(uint8_t)(int8_t)a) << (8 * j);
        p1 |= ((uint32_t)(uint8_t)(int8_t)b) << (8 * j);
    }
}

__global__ void quant_f32(const float* __restrict__ src, int8_t* __restrict__ d0,
                          int8_t* __restrict__ d1, float* __restrict__ sc, int nrows)
{
    int row = blockIdx.x * 8 + (threadIdx.x >> 5);
    if (row >= nrows) return;
    int lane = threadIdx.x & 31;
    const float4* p = (const float4*)(src + (size_t)row * K_) + lane;
    float4 v[8];
    float amax = 0.0f;
    #pragma unroll
    for (int i = 0; i < 8; i++) {
        v[i] = p[i * 32];
        amax = fmaxf(amax, fmaxf(fmaxf(fabsf(v[i].x), fabsf(v[i].y)),
                                 fmaxf(fabsf(v[i].z), fabsf(v[i].w))));
    }
    #pragma unroll
    for (int off = 16; off; off >>= 1)
        amax = fmaxf(amax, __shfl_xor_sync(0xffffffffu, amax, off));
    float inv = amax > 0.0f ? 127.0f / amax : 0.0f;
    if (lane == 0) sc[row] = amax > 0.0f ? amax / 127.0f : 0.0f;
    uint32_t* q0 = (uint32_t*)(d0 + (size_t)row * K_) + lane;
    uint32_t* q1 = (uint32_t*)(d1 + (size_t)row * K_) + lane;
    #pragma unroll
    for (int i = 0; i < 8; i++) {
        float f[4] = {v[i].x * inv, v[i].y * inv, v[i].z * inv, v[i].w * inv};
        uint32_t p0, p1;
        quant_store(f, p0, p1);
        q0[i * 32] = p0;
        q1[i * 32] = p1;
    }
}

__global__ void quant_pair(const bf16* __restrict__ hi, const bf16* __restrict__ lo,
                           int8_t* __restrict__ d0, int8_t* __restrict__ d1,
                           float* __restrict__ sc, int nrows)
{
    int row = blockIdx.x * 8 + (threadIdx.x >> 5);
    if (row >= nrows) return;
    int lane = threadIdx.x & 31;
    const uint2* ph = (const uint2*)(hi + (size_t)row * K_) + lane;
    const uint2* pl = (const uint2*)(lo + (size_t)row * K_) + lane;
    float v[8][4];
    float amax = 0.0f;
    #pragma unroll
    for (int i = 0; i < 8; i++) {
        uint2 hv = ph[i * 32], lv = pl[i * 32];
        __nv_bfloat162 h0 = *(__nv_bfloat162*)&hv.x, h1 = *(__nv_bfloat162*)&hv.y;
        __nv_bfloat162 l0 = *(__nv_bfloat162*)&lv.x, l1 = *(__nv_bfloat162*)&lv.y;
        v[i][0] = __bfloat162float(h0.x) + __bfloat162float(l0.x);
        v[i][1] = __bfloat162float(h0.y) + __bfloat162float(l0.y);
        v[i][2] = __bfloat162float(h1.x) + __bfloat162float(l1.x);
        v[i][3] = __bfloat162float(h1.y) + __bfloat162float(l1.y);
        #pragma unroll
        for (int j = 0; j < 4; j++) amax = fmaxf(amax, fabsf(v[i][j]));
    }
    #pragma unroll
    for (int off = 16; off; off >>= 1)
        amax = fmaxf(amax, __shfl_xor_sync(0xffffffffu, amax, off));
    float inv = amax > 0.0f ? 127.0f / amax : 0.0f;
    if (lane == 0) sc[row] = amax > 0.0f ? amax / 127.0f : 0.0f;
    uint32_t* q0 = (uint32_t*)(d0 + (size_t)row * K_) + lane;
    uint32_t* q1 = (uint32_t*)(d1 + (size_t)row * K_) + lane;
    #pragma unroll
    for (int i = 0; i < 8; i++) {
        float f[4] = {v[i][0] * inv, v[i][1] * inv, v[i][2] * inv, v[i][3] * inv};
        uint32_t p0, p1;
        quant_store(f, p0, p1);
        q0[i * 32] = p0;
        q1[i * 32] = p1;
    }
}

// ---------------------------------------------------------------------------
// int8 GEMM: C[M,N] = A[M,1024] @ B[N,1024]^T via IMMA m16n8k32, 3 passes
// (d0d0 -> acc0; d0d1 + d1d0 -> acc1). CTA 128x128, 8 warps (2x4, warp tile
// 64x32), BK=64, 3-stage cp.async. Epilogue: sA*sB*(acc0 + acc1/254).
// ---------------------------------------------------------------------------
#define PKQ 80
#define TSZ (128 * PKQ)          // 10240
#define QSTAGE (4 * TSZ)         // 40960 (Ad0|Ad1|Bd0|Bd1)
#define QSMEM (3 * QSTAGE)       // 122880
#define NCHQ 16                  // 1024/64

template<bool SPLIT>
__global__ __launch_bounds__(256) void gemm_i8(
    const int8_t* __restrict__ Ad0, const int8_t* __restrict__ Ad1,
    const float* __restrict__ sA,
    const int8_t* __restrict__ Bd0, const int8_t* __restrict__ Bd1,
    const float* __restrict__ sB,
    float* __restrict__ Cf, bf16* __restrict__ Chi, bf16* __restrict__ Clo, int N)
{
    extern __shared__ char smx[];
    const int tid = threadIdx.x, lane = tid & 31, wid = tid >> 5;
    const int bm = blockIdx.y * 128, bn = blockIdx.x * 128;
    const int m0 = (wid >> 2) * 64, n0 = (wid & 3) * 32;

    const int8_t* srcs[4] = { Ad0 + (size_t)bm * K_, Ad1 + (size_t)bm * K_,
                              Bd0 + (size_t)bn * K_, Bd1 + (size_t)bn * K_ };

    int acc0[4][4][4], acc1[4][4][4];
    #pragma unroll
    for (int i = 0; i < 4; i++)
        #pragma unroll
        for (int j = 0; j < 4; j++)
            #pragma unroll
            for (int q = 0; q < 4; q++) { acc0[i][j][q] = 0; acc1[i][j][q] = 0; }

    auto load_stage = [&](int s, int k0) {
        char* base = smx + s * QSTAGE;
        #pragma unroll
        for (int t4 = 0; t4 < 4; t4++) {
            #pragma unroll
            for (int i = 0; i < 2; i++) {
                int idx = tid + i * 256;         // 0..511
                int r = idx >> 2, c = idx & 3;
                cp16(sptr(base + t4 * TSZ + r * PKQ + c * 16),
                     srcs[t4] + (size_t)r * K_ + k0 + c * 16);
            }
        }
    };

    load_stage(0, 0);  CP_COMMIT();
    load_stage(1, 64); CP_COMMIT();

    const int r8 = lane & 7;
    const int arow = ((lane >> 3) & 1) * 8, acol = (lane >> 4) * 16;
    const int brow = (lane >> 4) * 8,       bcol = ((lane >> 3) & 1) * 16;

    for (int kc = 0; kc < NCHQ; kc++) {
        if (kc == NCHQ - 1) { CP_WAIT(0); } else { CP_WAIT(1); }
        __syncthreads();
        if (kc + 2 < NCHQ) {
            load_stage((kc + 2) % 3, (kc + 2) * 64);
            CP_COMMIT();
        }

        char* base = smx + (kc % 3) * QSTAGE;
        uint32_t bA0 = sptr(base),        bA1 = bA0 + TSZ;
        uint32_t bB0 = bA0 + 2 * TSZ,     bB1 = bA0 + 3 * TSZ;

        #pragma unroll
        for (int ks = 0; ks < 2; ks++) {
            uint32_t a0f[4][4], a1f[4][4];
            #pragma unroll
            for (int mt = 0; mt < 4; mt++) {
                uint32_t off = (uint32_t)(m0 + mt * 16 + r8 + arow) * PKQ + ks * 32 + acol;
                ldsm4(bA0 + off, a0f[mt]);
                ldsm4(bA1 + off, a1f[mt]);
            }
            uint32_t b0f[2][4], b1f[2][4];
            #pragma unroll
            for (int gb = 0; gb < 2; gb++) {
                uint32_t off = (uint32_t)(n0 + gb * 16 + r8 + brow) * PKQ + ks * 32 + bcol;
                ldsm4(bB0 + off, b0f[gb]);
                ldsm4(bB1 + off, b1f[gb]);
            }
            #pragma unroll
            for (int mt = 0; mt < 4; mt++)
                #pragma unroll
                for (int j = 0; j < 4; j++) {
                    int gb = j >> 1, ix = (j & 1) * 2;
                    imma(acc0[mt][j], a0f[mt], b0f[gb][ix], b0f[gb][ix + 1]);
                    imma(acc1[mt][j], a0f[mt], b1f[gb][ix], b1f[gb][ix + 1]);
                    imma(acc1[mt][j], a1f[mt], b0f[gb][ix], b0f[gb][ix + 1]);
                }
        }
    }

    // Epilogue: rescale, write
    #pragma unroll
    for (int mt = 0; mt < 4; mt++) {
        int row0 = bm + m0 + mt * 16 + (lane >> 2);
        int row1 = row0 + 8;
        float sa0 = sA[row0], sa1 = sA[row1];
        #pragma unroll
        for (int j = 0; j < 4; j++) {
            int col = bn + n0 + j * 8 + (lane & 3) * 2;
            float sb0 = sB[col], sb1 = sB[col + 1];
            float v00 = sa0 * sb0 * ((float)acc0[mt][j][0] + (float)acc1[mt][j][0] * INV254);
            float v01 = sa0 * sb1 * ((float)acc0[mt][j][1] + (float)acc1[mt][j][1] * INV254);
            float v10 = sa1 * sb0 * ((float)acc0[mt][j][2] + (float)acc1[mt][j][2] * INV254);
            float v11 = sa1 * sb1 * ((float)acc0[mt][j][3] + (float)acc1[mt][j][3] * INV254);
            if (SPLIT) {
                uint32_t h0, l0, h1, l1;
                split_pack(v00, v01, h0, l0);
                split_pack(v10, v11, h1, l1);
                *(uint32_t*)(Chi + (size_t)row0 * N + col) = h0;
                *(uint32_t*)(Clo + (size_t)row0 * N + col) = l0;
                *(uint32_t*)(Chi + (size_t)row1 * N + col) = h1;
                *(uint32_t*)(Clo + (size_t)row1 * N + col) = l1;
            } else {
                *(float2*)(Cf + (size_t)row0 * N + col) = make_float2(v00, v01);
                *(float2*)(Cf + (size_t)row1 * N + col) = make_float2(v10, v11);
            }
        }
    }
}

// ---------------------------------------------------------------------------
// Flash attention: bf16 3-pass hi/lo, 8 warps, 128-q tile, double-buffered
// K/V, SW128 swizzled smem (96 KB) -> 2 CTAs/SM.  (unchanged from R7)
// ---------------------------------------------------------------------------
#define SQH 0
#define SQL 16384
#define SKV0 32768
#define KVSTAGE 32768
#define ATT_SMEM (SKV0 + 2 * KVSTAGE)   // 98304

__global__ __launch_bounds__(256, 2) void attn_mma()
{
    extern __shared__ char smx[];
    const int tid = threadIdx.x, lane = tid & 31, warp = tid >> 5;
    const int qt = blockIdx.x;
    const int b  = blockIdx.y >> 4;
    const int h  = blockIdx.y & 15;
    const int qrow0 = b * S_ + qt * 128;

    const bf16* qh = g_qhi + (size_t)qrow0 * QKV_N + h * DH_;
    const bf16* ql = g_qlo + (size_t)qrow0 * QKV_N + h * DH_;
    const bf16* kh = g_qhi + (size_t)(b * S_) * QKV_N + D_ + h * DH_;
    const bf16* kl = g_qlo + (size_t)(b * S_) * QKV_N + D_ + h * DH_;
    const bf16* vh = g_qhi + (size_t)(b * S_) * QKV_N + 2 * D_ + h * DH_;
    const bf16* vl = g_qlo + (size_t)(b * S_) * QKV_N + 2 * D_ + h * DH_;

    uint32_t sb = sptr(smx);

    #pragma unroll
    for (int i = 0; i < 4; i++) {
        int idx = tid + i * 256;
        int r = idx >> 3, c = idx & 7;
        uint32_t so = sw128((uint32_t)(r * 128 + c * 16));
        cp16(sb + SQH + so, qh + (size_t)r * QKV_N + c * 8);
        cp16(sb + SQL + so, ql + (size_t)r * QKV_N + c * 8);
    }
    CP_COMMIT();

    auto ld_kv = [&](int s, int krow) {
        uint32_t base = sb + SKV0 + s * KVSTAGE;
        #pragma unroll
        for (int i = 0; i < 2; i++) {
            int idx = tid + i * 256;
            int r = idx >> 3, c = idx & 7;
            size_t go = (size_t)(krow + r) * QKV_N + c * 8;
            uint32_t so = sw128((uint32_t)(r * 128 + c * 16));
            cp16(base + so,         kh + go);
            cp16(base + 8192 + so,  kl + go);
            cp16(base + 16384 + so, vh + go);
            cp16(base + 24576 + so, vl + go);
        }
    };

    ld_kv(0, 0);
    CP_COMMIT();
    CP_WAIT(1);
    __syncthreads();

    const int row_in = lane & 7, g = lane >> 3;

    uint32_t qa_h[4][4], qa_l[4][4];
    #pragma unroll
    for (int ks = 0; ks < 4; ks++) {
        uint32_t off = sw128((uint32_t)(warp * 16 + row_in + (g & 1) * 8) * 128
                             + (ks * 16 + (g >> 1) * 8) * 2);
        ldsm4(sb + SQH + off, qa_h[ks]);
        ldsm4(sb + SQL + off, qa_l[ks]);
    }

    float m0 = -1e30f, m1 = -1e30f, l0 = 0.0f, l1 = 0.0f;
    float O[8][4];
    #pragma unroll
    for (int nt = 0; nt < 8; nt++)
        #pragma unroll
        for (int q = 0; q < 4; q++) O[nt][q] = 0.0f;

    for (int kt = 0; kt < S_ / 64; kt++) {
        if (kt + 1 < S_ / 64) {
            ld_kv((kt + 1) & 1, (kt + 1) * 64);
            CP_COMMIT();
            CP_WAIT(1);
        } else {
            CP_WAIT(0);
        }
        __syncthreads();

        uint32_t kvb = sb + SKV0 + (kt & 1) * KVSTAGE;

        float s[8][4];
        #pragma unroll
        for (int nt = 0; nt < 8; nt++)
            #pragma unroll
            for (int q = 0; q < 4; q++) s[nt][q] = 0.0f;

        #pragma unroll
        for (int ks = 0; ks < 4; ks++) {
            #pragma unroll
            for (int gb = 0; gb < 4; gb++) {
                uint32_t bh[4], bl[4];
                uint32_t off = sw128((uint32_t)(gb * 16 + ((g >> 1) & 1) * 8 + row_in) * 128
                                     + (ks * 16 + (g & 1) * 8) * 2);
                ldsm4(kvb + off, bh);
                ldsm4(kvb + 8192 + off, bl);
                #pragma unroll
                for (int hf = 0; hf < 2; hf++) {
                    int nt = gb * 2 + hf, ix = hf * 2;
                    mma_bf16(s[nt], qa_h[ks], bh[ix], bh[ix + 1]);
                    mma_bf16(s[nt], qa_h[ks], bl[ix], bl[ix + 1]);
                    mma_bf16(s[nt], qa_l[ks], bh[ix], bh[ix + 1]);
                }
            }
        }

        float mx0 = -1e30f, mx1 = -1e30f;
        #pragma unroll
        for (int nt = 0; nt < 8; nt++) {
            #pragma unroll
            for (int q = 0; q < 4; q++) s[nt][q] *= SCALE;
            mx0 = fmaxf(mx0, fmaxf(s[nt][0], s[nt][1]));
            mx1 = fmaxf(mx1, fmaxf(s[nt][2], s[nt][3]));
        }
        mx0 = fmaxf(mx0, __shfl_xor_sync(0xffffffffu, mx0, 1));
        mx0 = fmaxf(mx0, __shfl_xor_sync(0xffffffffu, mx0, 2));
        mx1 = fmaxf(mx1, __shfl_xor_sync(0xffffffffu, mx1, 1));
        mx1 = fmaxf(mx1, __shfl_xor_sync(0xffffffffu, mx1, 2));

        float mn0 = fmaxf(m0, mx0), mn1 = fmaxf(m1, mx1);
        float c0 = __expf(m0 - mn0), c1 = __expf(m1 - mn1);
        float sum0 = 0.0f, sum1 = 0.0f;
        #pragma unroll
        for (int nt = 0; nt < 8; nt++) {
            s[nt][0] = __expf(s[nt][0] - mn0); sum0 += s[nt][0];
            s[nt][1] = __expf(s[nt][1] - mn0); sum0 += s[nt][1];
            s[nt][2] = __expf(s[nt][2] - mn1); sum1 += s[nt][2];
            s[nt][3] = __expf(s[nt][3] - mn1); sum1 += s[nt][3];
        }
        sum0 += __shfl_xor_sync(0xffffffffu, sum0, 1);
        sum0 += __shfl_xor_sync(0xffffffffu, sum0, 2);
        sum1 += __shfl_xor_sync(0xffffffffu, sum1, 1);
        sum1 += __shfl_xor_sync(0xffffffffu, sum1, 2);
        l0 = l0 * c0 + sum0;
        l1 = l1 * c1 + sum1;
        m0 = mn0; m1 = mn1;
        #pragma unroll
        for (int nt = 0; nt < 8; nt++) {
            O[nt][0] *= c0; O[nt][1] *= c0;
            O[nt][2] *= c1; O[nt][3] *= c1;
        }

        #pragma unroll
        for (int j = 0; j < 4; j++) {
            uint32_t pah[4], pal[4];
            split_pack(s[2 * j][0],     s[2 * j][1],     pah[0], pal[0]);
            split_pack(s[2 * j][2],     s[2 * j][3],     pah[1], pal[1]);
            split_pack(s[2 * j + 1][0], s[2 * j + 1][1], pah[2], pal[2]);
            split_pack(s[2 * j + 1][2], s[2 * j + 1][3], pah[3], pal[3]);

            #pragma unroll
            for (int gv = 0; gv < 4; gv++) {
                uint32_t vhf[4], vlf[4];
                uint32_t off = sw128((uint32_t)(j * 16 + (g & 1) * 8 + row_in) * 128
                                     + (gv * 16 + (g >> 1) * 8) * 2);
                ldsm4t(kvb + 16384 + off, vhf);
                ldsm4t(kvb + 24576 + off, vlf);
                #pragma unroll
                for (int hf = 0; hf < 2; hf++) {
                    int nt = gv * 2 + hf, ix = hf * 2;
                    mma_bf16(O[nt], pah, vhf[ix], vhf[ix + 1]);
                    mma_bf16(O[nt], pah, vlf[ix], vlf[ix + 1]);
                    mma_bf16(O[nt], pal, vhf[ix], vhf[ix + 1]);
                }
            }
        }
        __syncthreads();
    }

    float inv0 = 1.0f / (l0 + 1e-6f);
    float inv1 = 1.0f / (l1 + 1e-6f);
    int r0g = qrow0 + warp * 16 + (lane >> 2);
    #pragma unroll
    for (int nt = 0; nt < 8; nt++) {
        int col = h * DH_ + nt * 8 + (lane & 3) * 2;
        uint32_t h0, lo0, h1, lo1;
        split_pack(O[nt][0] * inv0, O[nt][1] * inv0, h0, lo0);
        split_pack(O[nt][2] * inv1, O[nt][3] * inv1, h1, lo1);
        *(uint32_t*)(g_ahi + (size_t)r0g * D_ + col) = h0;
        *(uint32_t*)(g_alo + (size_t)r0g * D_ + col) = lo0;
        *(uint32_t*)(g_ahi + (size_t)(r0g + 8) * D_ + col) = h1;
        *(uint32_t*)(g_alo + (size_t)(r0g + 8) * D_ + col) = lo1;
    }
}

// ---------------------------------------------------------------------------
// Launch
// ---------------------------------------------------------------------------
extern "C" void kernel_launch(void* const* d_in, const int* in_sizes, int n_in,
                              void* d_out, int out_size)
{
    const float* x    = (const float*)d_in[0];
    const float* Wqkv = (const float*)d_in[1];
    const float* Wout = (const float*)d_in[2];
    float* out = (float*)d_out;

    int8_t *xd0, *xd1, *wqd0, *wqd1, *wod0, *wod1, *ad0, *ad1;
    float *xs, *wqs, *wos, *as;
    bf16 *qhi, *qlo, *ahi, *alo;
    cudaGetSymbolAddress((void**)&xd0,  g_xd0);
    cudaGetSymbolAddress((void**)&xd1,  g_xd1);
    cudaGetSymbolAddress((void**)&xs,   g_xs);
    cudaGetSymbolAddress((void**)&wqd0, g_wqd0);
    cudaGetSymbolAddress((void**)&wqd1, g_wqd1);
    cudaGetSymbolAddress((void**)&wqs,  g_wqs);
    cudaGetSymbolAddress((void**)&wod0, g_wod0);
    cudaGetSymbolAddress((void**)&wod1, g_wod1);
    cudaGetSymbolAddress((void**)&wos,  g_wos);
    cudaGetSymbolAddress((void**)&ad0,  g_ad0);
    cudaGetSymbolAddress((void**)&ad1,  g_ad1);
    cudaGetSymbolAddress((void**)&as,   g_as);
    cudaGetSymbolAddress((void**)&qhi,  g_qhi);
    cudaGetSymbolAddress((void**)&qlo,  g_qlo);
    cudaGetSymbolAddress((void**)&ahi,  g_ahi);
    cudaGetSymbolAddress((void**)&alo,  g_alo);

    cudaFuncSetAttribute(gemm_i8<true>,
                         cudaFuncAttributeMaxDynamicSharedMemorySize, QSMEM);
    cudaFuncSetAttribute(gemm_i8<false>,
                         cudaFuncAttributeMaxDynamicSharedMemorySize, QSMEM);
    cudaFuncSetAttribute(attn_mma,
                         cudaFuncAttributeMaxDynamicSharedMemorySize, ATT_SMEM);

    // 0) quantize inputs (row-wise int8 two-digit)
    quant_f32<<<M_TOT / 8, 256>>>(x,    xd0,  xd1,  xs,  M_TOT);
    quant_f32<<<QKV_N / 8, 256>>>(Wqkv, wqd0, wqd1, wqs, QKV_N);
    quant_f32<<<D_ / 8,    256>>>(Wout, wod0, wod1, wos, D_);

    // 1) qkv = x @ Wqkv^T (IMMA) -> bf16 hi/lo for attention
    gemm_i8<true><<<dim3(QKV_N / 128, M_TOT / 128), 256, QSMEM>>>(
        xd0, xd1, xs, wqd0, wqd1, wqs, nullptr, qhi, qlo, QKV_N);

    // 2) attention (bf16 3-pass) -> g_ahi/g_alo
    attn_mma<<<dim3(S_ / 128, B_ * H_), 256, ATT_SMEM>>>();

    // 3) quantize attention output rows
    quant_pair<<<M_TOT / 8, 256>>>(ahi, alo, ad0, ad1, as, M_TOT);

    // 4) out = attn @ Wout^T (IMMA) -> fp32
    gemm_i8<false><<<dim3(D_ / 128, M_TOT / 128), 256, QSMEM>>>(
        ad0, ad1, as, wod0, wod1, wos, out, nullptr, nullptr, D_);
}

// round 9
// speedup vs baseline: 1.5822x; 1.5822x over previous
#include <cuda_runtime.h>
#include <cuda_fp16.h>
#include <math.h>
#include <stdint.h>

// ---------------------------------------------------------------------------
// Problem constants
// ---------------------------------------------------------------------------
#define B_    2
#define S_    2048
#define D_    1024
#define H_    16
#define DH_   64
#define M_TOT (B_ * S_)      // 4096
#define QKV_N (3 * D_)       // 3072
#define K_    1024
#define SCALE 0.125f
#define LOSC  1024.0f
#define INVLO (1.0f / 1024.0f)

// ---------------------------------------------------------------------------
// Scratch (__device__ globals): fp16 two-digit (v = h + l/1024)
// ---------------------------------------------------------------------------
__device__ __half g_xh[M_TOT * D_],  g_xl[M_TOT * D_];
__device__ __half g_wqh[QKV_N * D_], g_wql[QKV_N * D_];
__device__ __half g_woh[D_ * D_],    g_wol[D_ * D_];
__device__ __half g_qh[M_TOT * QKV_N], g_ql[M_TOT * QKV_N];  // qkv
__device__ __half g_ah[M_TOT * D_],  g_al[M_TOT * D_];       // attn out

// ---------------------------------------------------------------------------
// Helpers
// ---------------------------------------------------------------------------
__device__ __forceinline__ uint32_t sptr(const void* p) {
    return (uint32_t)__cvta_generic_to_shared(p);
}
__device__ __forceinline__ void cp16(uint32_t d, const void* s) {
    asm volatile("cp.async.cg.shared.global [%0], [%1], 16;" :: "r"(d), "l"(s));
}
#define CP_COMMIT() asm volatile("cp.async.commit_group;" ::: "memory")
#define CP_WAIT(n)  asm volatile("cp.async.wait_group %0;" :: "n"(n) : "memory")

__device__ __forceinline__ uint32_t sw128(uint32_t o) {   // Swizzle<3,4,3>
    return o ^ ((o >> 3) & 0x70);
}
__device__ __forceinline__ void ldsm4(uint32_t a, uint32_t r[4]) {
    asm volatile("ldmatrix.sync.aligned.m8n8.x4.shared.b16 {%0,%1,%2,%3}, [%4];"
                 : "=r"(r[0]), "=r"(r[1]), "=r"(r[2]), "=r"(r[3]) : "r"(a));
}
__device__ __forceinline__ void ldsm4t(uint32_t a, uint32_t r[4]) {
    asm volatile("ldmatrix.sync.aligned.m8n8.x4.trans.shared.b16 {%0,%1,%2,%3}, [%4];"
                 : "=r"(r[0]), "=r"(r[1]), "=r"(r[2]), "=r"(r[3]) : "r"(a));
}
// f32-accum fp16 mma (dominant pass)
__device__ __forceinline__ void mma_f32a(float c[4], const uint32_t a[4],
                                         uint32_t b0, uint32_t b1) {
    asm volatile(
        "mma.sync.aligned.m16n8k16.row.col.f32.f16.f16.f32 "
        "{%0,%1,%2,%3}, {%4,%5,%6,%7}, {%8,%9}, {%0,%1,%2,%3};"
        : "+f"(c[0]), "+f"(c[1]), "+f"(c[2]), "+f"(c[3])
        : "r"(a[0]), "r"(a[1]), "r"(a[2]), "r"(a[3]), "r"(b0), "r"(b1));
}
// f16-accum fp16 mma (compensation passes)
__device__ __forceinline__ void mma_f16a(uint32_t c[2], const uint32_t a[4],
                                         uint32_t b0, uint32_t b1) {
    asm volatile(
        "mma.sync.aligned.m16n8k16.row.col.f16.f16.f16.f16 "
        "{%0,%1}, {%2,%3,%4,%5}, {%6,%7}, {%0,%1};"
        : "+r"(c[0]), "+r"(c[1])
        : "r"(a[0]), "r"(a[1]), "r"(a[2]), "r"(a[3]), "r"(b0), "r"(b1));
}
// pack (a,b) -> fp16x2 hi + fp16x2 lo (lo = residual * 1024)
__device__ __forceinline__ void split_pack(float a, float b, uint32_t& hi, uint32_t& lo) {
    __half2 hp = __floats2half2_rn(a, b);
    float ra = (a - __half2float(__low2half(hp)))  * LOSC;
    float rb = (b - __half2float(__high2half(hp))) * LOSC;
    __half2 lp = __floats2half2_rn(ra, rb);
    hi = *(uint32_t*)&hp;
    lo = *(uint32_t*)&lp;
}
__device__ __forceinline__ float mixlo(uint32_t r)  { return __half2float(__low2half(*(__half2*)&r)); }
__device__ __forceinline__ float mixhi(uint32_t r)  { return __half2float(__high2half(*(__half2*)&r)); }

// ---------------------------------------------------------------------------
// Split: fp32 -> fp16 hi + fp16 lo*1024
// ---------------------------------------------------------------------------
__global__ void split_f16(const float* __restrict__ src,
                          __half* __restrict__ hi, __half* __restrict__ lo, int n)
{
    for (int i = blockIdx.x * blockDim.x + threadIdx.x; i < n; i += gridDim.x * blockDim.x) {
        float v = src[i];
        __half h = __float2half_rn(v);
        hi[i] = h;
        lo[i] = __float2half_rn((v - __half2float(h)) * LOSC);
    }
}

// ---------------------------------------------------------------------------
// GEMM: C[M,N] = A[M,1024] @ B[N,1024]^T. fp16 two-digit:
// acc_f32 += Ah*Bh ;  mix_f16 += Ah*Bl' + Al'*Bh ; C = acc + mix/1024.
// CTA 128x128, 8 warps (2x4, warp tile 64x32), BK=32, 3-stage cp.async.
// ---------------------------------------------------------------------------
#define PKB 80
#define TSZ (128 * PKB)          // 10240 per tile (Ah|Al|Bh|Bl)
#define GSTAGE (4 * TSZ)         // 40960
#define GEMM_SMEM (3 * GSTAGE)   // 122880
#define NCHUNK 32                // 1024/32

template<bool SPLIT>
__global__ __launch_bounds__(256) void gemm_mma(
    const __half* __restrict__ Ah, const __half* __restrict__ Al,
    const __half* __restrict__ Bh, const __half* __restrict__ Bl,
    float* __restrict__ Cf, __half* __restrict__ Chi, __half* __restrict__ Clo, int N)
{
    extern __shared__ char smx[];
    const int tid = threadIdx.x, lane = tid & 31, wid = tid >> 5;
    const int bm = blockIdx.y * 128, bn = blockIdx.x * 128;
    const int m0 = (wid >> 2) * 64, n0 = (wid & 3) * 32;

    const __half* srcs[4] = { Ah + (size_t)bm * K_, Al + (size_t)bm * K_,
                              Bh + (size_t)bn * K_, Bl + (size_t)bn * K_ };

    float acc[4][4][4];
    uint32_t mix[4][4][2];
    #pragma unroll
    for (int i = 0; i < 4; i++)
        #pragma unroll
        for (int j = 0; j < 4; j++) {
            #pragma unroll
            for (int q = 0; q < 4; q++) acc[i][j][q] = 0.0f;
            mix[i][j][0] = 0u; mix[i][j][1] = 0u;
        }

    auto load_stage = [&](int s, int k0) {
        char* base = smx + s * GSTAGE;
        #pragma unroll
        for (int t4 = 0; t4 < 4; t4++) {
            #pragma unroll
            for (int i = 0; i < 2; i++) {
                int idx = tid + i * 256;         // 0..511
                int r = idx >> 2, c = idx & 3;
                cp16(sptr(base + t4 * TSZ + r * PKB + c * 16),
                     srcs[t4] + (size_t)r * K_ + k0 + c * 8);
            }
        }
    };

    load_stage(0, 0);  CP_COMMIT();
    load_stage(1, 32); CP_COMMIT();

    const int row_in = lane & 7, g = lane >> 3;

    for (int kc = 0; kc < NCHUNK; kc++) {
        if (kc == NCHUNK - 1) { CP_WAIT(0); } else { CP_WAIT(1); }
        __syncthreads();
        if (kc + 2 < NCHUNK) {
            load_stage((kc + 2) % 3, (kc + 2) * 32);
            CP_COMMIT();
        }

        char* base = smx + (kc % 3) * GSTAGE;
        uint32_t bAh = sptr(base),    bAl = bAh + TSZ;
        uint32_t bBh = bAh + 2 * TSZ, bBl = bAh + 3 * TSZ;

        #pragma unroll
        for (int ks = 0; ks < 2; ks++) {
            uint32_t ahf[4][4], alf[4][4];
            #pragma unroll
            for (int mt = 0; mt < 4; mt++) {
                uint32_t off = (uint32_t)(m0 + mt * 16 + row_in + (g & 1) * 8) * PKB
                             + (ks * 16 + (g >> 1) * 8) * 2;
                ldsm4(bAh + off, ahf[mt]);
                ldsm4(bAl + off, alf[mt]);
            }
            #pragma unroll
            for (int gb = 0; gb < 2; gb++) {
                uint32_t bhf[4], blf[4];
                uint32_t off = (uint32_t)(n0 + gb * 16 + ((g >> 1) & 1) * 8 + row_in) * PKB
                             + (ks * 16 + (g & 1) * 8) * 2;
                ldsm4(bBh + off, bhf);
                ldsm4(bBl + off, blf);
                #pragma unroll
                for (int mt = 0; mt < 4; mt++)
                    #pragma unroll
                    for (int hf = 0; hf < 2; hf++) {
                        int nt = gb * 2 + hf, ix = hf * 2;
                        mma_f32a(acc[mt][nt], ahf[mt], bhf[ix], bhf[ix + 1]);
                        mma_f16a(mix[mt][nt], ahf[mt], blf[ix], blf[ix + 1]);
                        mma_f16a(mix[mt][nt], alf[mt], bhf[ix], bhf[ix + 1]);
                    }
            }
        }
    }

    // Epilogue: merge mix, write
    #pragma unroll
    for (int mt = 0; mt < 4; mt++)
        #pragma unroll
        for (int nt = 0; nt < 4; nt++) {
            int row = bm + m0 + mt * 16 + (lane >> 2);
            int col = bn + n0 + nt * 8 + (lane & 3) * 2;
            float v0 = acc[mt][nt][0] + mixlo(mix[mt][nt][0]) * INVLO;
            float v1 = acc[mt][nt][1] + mixhi(mix[mt][nt][0]) * INVLO;
            float v2 = acc[mt][nt][2] + mixlo(mix[mt][nt][1]) * INVLO;
            float v3 = acc[mt][nt][3] + mixhi(mix[mt][nt][1]) * INVLO;
            if (SPLIT) {
                uint32_t h0, l0, h1, l1;
                split_pack(v0, v1, h0, l0);
                split_pack(v2, v3, h1, l1);
                *(uint32_t*)(Chi + (size_t)row * N + col) = h0;
                *(uint32_t*)(Clo + (size_t)row * N + col) = l0;
                *(uint32_t*)(Chi + (size_t)(row + 8) * N + col) = h1;
                *(uint32_t*)(Clo + (size_t)(row + 8) * N + col) = l1;
            } else {
                *(float2*)(Cf + (size_t)row * N + col) = make_float2(v0, v1);
                *(float2*)(Cf + (size_t)(row + 8) * N + col) = make_float2(v2, v3);
            }
        }
}

// ---------------------------------------------------------------------------
// Flash attention: fp16 two-digit, 8 warps, 128-q tile, double-buffered K/V,
// SW128 swizzled smem (96 KB).
// ---------------------------------------------------------------------------
#define SQH 0
#define SQL 16384
#define SKV0 32768
#define KVSTAGE 32768
#define ATT_SMEM (SKV0 + 2 * KVSTAGE)   // 98304

__global__ __launch_bounds__(256) void attn_mma()
{
    extern __shared__ char smx[];
    const int tid = threadIdx.x, lane = tid & 31, warp = tid >> 5;
    const int qt = blockIdx.x;
    const int b  = blockIdx.y >> 4;
    const int h  = blockIdx.y & 15;
    const int qrow0 = b * S_ + qt * 128;

    const __half* qh = g_qh + (size_t)qrow0 * QKV_N + h * DH_;
    const __half* ql = g_ql + (size_t)qrow0 * QKV_N + h * DH_;
    const __half* kh = g_qh + (size_t)(b * S_) * QKV_N + D_ + h * DH_;
    const __half* kl = g_ql + (size_t)(b * S_) * QKV_N + D_ + h * DH_;
    const __half* vh = g_qh + (size_t)(b * S_) * QKV_N + 2 * D_ + h * DH_;
    const __half* vl = g_ql + (size_t)(b * S_) * QKV_N + 2 * D_ + h * DH_;

    uint32_t sb = sptr(smx);

    #pragma unroll
    for (int i = 0; i < 4; i++) {
        int idx = tid + i * 256;
        int r = idx >> 3, c = idx & 7;
        uint32_t so = sw128((uint32_t)(r * 128 + c * 16));
        cp16(sb + SQH + so, qh + (size_t)r * QKV_N + c * 8);
        cp16(sb + SQL + so, ql + (size_t)r * QKV_N + c * 8);
    }
    CP_COMMIT();

    auto ld_kv = [&](int s, int krow) {
        uint32_t base = sb + SKV0 + s * KVSTAGE;
        #pragma unroll
        for (int i = 0; i < 2; i++) {
            int idx = tid + i * 256;
            int r = idx >> 3, c = idx & 7;
            size_t go = (size_t)(krow + r) * QKV_N + c * 8;
            uint32_t so = sw128((uint32_t)(r * 128 + c * 16));
            cp16(base + so,         kh + go);
            cp16(base + 8192 + so,  kl + go);
            cp16(base + 16384 + so, vh + go);
            cp16(base + 24576 + so, vl + go);
        }
    };

    ld_kv(0, 0);
    CP_COMMIT();
    CP_WAIT(1);
    __syncthreads();

    const int row_in = lane & 7, g = lane >> 3;

    uint32_t qa_h[4][4], qa_l[4][4];
    #pragma unroll
    for (int ks = 0; ks < 4; ks++) {
        uint32_t off = sw128((uint32_t)(warp * 16 + row_in + (g & 1) * 8) * 128
                             + (ks * 16 + (g >> 1) * 8) * 2);
        ldsm4(sb + SQH + off, qa_h[ks]);
        ldsm4(sb + SQL + off, qa_l[ks]);
    }

    float m0 = -1e30f, m1 = -1e30f, l0 = 0.0f, l1 = 0.0f;
    float O[8][4];
    #pragma unroll
    for (int nt = 0; nt < 8; nt++)
        #pragma unroll
        for (int q = 0; q < 4; q++) O[nt][q] = 0.0f;

    for (int kt = 0; kt < S_ / 64; kt++) {
        if (kt + 1 < S_ / 64) {
            ld_kv((kt + 1) & 1, (kt + 1) * 64);
            CP_COMMIT();
            CP_WAIT(1);
        } else {
            CP_WAIT(0);
        }
        __syncthreads();

        uint32_t kvb = sb + SKV0 + (kt & 1) * KVSTAGE;

        // ---- S = Q @ K^T ----
        float s[8][4];
        uint32_t smix[8][2];
        #pragma unroll
        for (int nt = 0; nt < 8; nt++) {
            #pragma unroll
            for (int q = 0; q < 4; q++) s[nt][q] = 0.0f;
            smix[nt][0] = 0u; smix[nt][1] = 0u;
        }

        #pragma unroll
        for (int ks = 0; ks < 4; ks++) {
            #pragma unroll
            for (int gb = 0; gb < 4; gb++) {
                uint32_t bh[4], bl[4];
                uint32_t off = sw128((uint32_t)(gb * 16 + ((g >> 1) & 1) * 8 + row_in) * 128
                                     + (ks * 16 + (g & 1) * 8) * 2);
                ldsm4(kvb + off, bh);
                ldsm4(kvb + 8192 + off, bl);
                #pragma unroll
                for (int hf = 0; hf < 2; hf++) {
                    int nt = gb * 2 + hf, ix = hf * 2;
                    mma_f32a(s[nt], qa_h[ks], bh[ix], bh[ix + 1]);
                    mma_f16a(smix[nt], qa_h[ks], bl[ix], bl[ix + 1]);
                    mma_f16a(smix[nt], qa_l[ks], bh[ix], bh[ix + 1]);
                }
            }
        }
        #pragma unroll
        for (int nt = 0; nt < 8; nt++) {
            s[nt][0] += mixlo(smix[nt][0]) * INVLO;
            s[nt][1] += mixhi(smix[nt][0]) * INVLO;
            s[nt][2] += mixlo(smix[nt][1]) * INVLO;
            s[nt][3] += mixhi(smix[nt][1]) * INVLO;
        }

        // ---- online softmax ----
        float mx0 = -1e30f, mx1 = -1e30f;
        #pragma unroll
        for (int nt = 0; nt < 8; nt++) {
            #pragma unroll
            for (int q = 0; q < 4; q++) s[nt][q] *= SCALE;
            mx0 = fmaxf(mx0, fmaxf(s[nt][0], s[nt][1]));
            mx1 = fmaxf(mx1, fmaxf(s[nt][2], s[nt][3]));
        }
        mx0 = fmaxf(mx0, __shfl_xor_sync(0xffffffffu, mx0, 1));
        mx0 = fmaxf(mx0, __shfl_xor_sync(0xffffffffu, mx0, 2));
        mx1 = fmaxf(mx1, __shfl_xor_sync(0xffffffffu, mx1, 1));
        mx1 = fmaxf(mx1, __shfl_xor_sync(0xffffffffu, mx1, 2));

        float mn0 = fmaxf(m0, mx0), mn1 = fmaxf(m1, mx1);
        float c0 = __expf(m0 - mn0), c1 = __expf(m1 - mn1);
        float sum0 = 0.0f, sum1 = 0.0f;
        #pragma unroll
        for (int nt = 0; nt < 8; nt++) {
            s[nt][0] = __expf(s[nt][0] - mn0); sum0 += s[nt][0];
            s[nt][1] = __expf(s[nt][1] - mn0); sum0 += s[nt][1];
            s[nt][2] = __expf(s[nt][2] - mn1); sum1 += s[nt][2];
            s[nt][3] = __expf(s[nt][3] - mn1); sum1 += s[nt][3];
        }
        sum0 += __shfl_xor_sync(0xffffffffu, sum0, 1);
        sum0 += __shfl_xor_sync(0xffffffffu, sum0, 2);
        sum1 += __shfl_xor_sync(0xffffffffu, sum1, 1);
        sum1 += __shfl_xor_sync(0xffffffffu, sum1, 2);
        l0 = l0 * c0 + sum0;
        l1 = l1 * c1 + sum1;
        m0 = mn0; m1 = mn1;
        #pragma unroll
        for (int nt = 0; nt < 8; nt++) {
            O[nt][0] *= c0; O[nt][1] *= c0;
            O[nt][2] *= c1; O[nt][3] *= c1;
        }

        // ---- O += P @ V ----
        uint32_t omix[8][2];
        #pragma unroll
        for (int nt = 0; nt < 8; nt++) { omix[nt][0] = 0u; omix[nt][1] = 0u; }

        #pragma unroll
        for (int j = 0; j < 4; j++) {
            uint32_t pah[4], pal[4];
            split_pack(s[2 * j][0],     s[2 * j][1],     pah[0], pal[0]);
            split_pack(s[2 * j][2],     s[2 * j][3],     pah[1], pal[1]);
            split_pack(s[2 * j + 1][0], s[2 * j + 1][1], pah[2], pal[2]);
            split_pack(s[2 * j + 1][2], s[2 * j + 1][3], pah[3], pal[3]);

            #pragma unroll
            for (int gv = 0; gv < 4; gv++) {
                uint32_t vhf[4], vlf[4];
                uint32_t off = sw128((uint32_t)(j * 16 + (g & 1) * 8 + row_in) * 128
                                     + (gv * 16 + (g >> 1) * 8) * 2);
                ldsm4t(kvb + 16384 + off, vhf);
                ldsm4t(kvb + 24576 + off, vlf);
                #pragma unroll
                for (int hf = 0; hf < 2; hf++) {
                    int nt = gv * 2 + hf, ix = hf * 2;
                    mma_f32a(O[nt], pah, vhf[ix], vhf[ix + 1]);
                    mma_f16a(omix[nt], pah, vlf[ix], vlf[ix + 1]);
                    mma_f16a(omix[nt], pal, vhf[ix], vhf[ix + 1]);
                }
            }
        }
        #pragma unroll
        for (int nt = 0; nt < 8; nt++) {
            O[nt][0] += mixlo(omix[nt][0]) * INVLO;
            O[nt][1] += mixhi(omix[nt][0]) * INVLO;
            O[nt][2] += mixlo(omix[nt][1]) * INVLO;
            O[nt][3] += mixhi(omix[nt][1]) * INVLO;
        }
        __syncthreads();
    }

    // ---- epilogue ----
    float inv0 = 1.0f / (l0 + 1e-6f);
    float inv1 = 1.0f / (l1 + 1e-6f);
    int r0g = qrow0 + warp * 16 + (lane >> 2);
    #pragma unroll
    for (int nt = 0; nt < 8; nt++) {
        int col = h * DH_ + nt * 8 + (lane & 3) * 2;
        uint32_t h0, lo0, h1, lo1;
        split_pack(O[nt][0] * inv0, O[nt][1] * inv0, h0, lo0);
        split_pack(O[nt][2] * inv1, O[nt][3] * inv1, h1, lo1);
        *(uint32_t*)(g_ah + (size_t)r0g * D_ + col) = h0;
        *(uint32_t*)(g_al + (size_t)r0g * D_ + col) = lo0;
        *(uint32_t*)(g_ah + (size_t)(r0g + 8) * D_ + col) = h1;
        *(uint32_t*)(g_al + (size_t)(r0g + 8) * D_ + col) = lo1;
    }
}

// ---------------------------------------------------------------------------
// Launch
// ---------------------------------------------------------------------------
extern "C" void kernel_launch(void* const* d_in, const int* in_sizes, int n_in,
                              void* d_out, int out_size)
{
    const float* x    = (const float*)d_in[0];
    const float* Wqkv = (const float*)d_in[1];
    const float* Wout = (const float*)d_in[2];
    float* out = (float*)d_out;

    __half *xh, *xl, *wqh, *wql, *woh, *wol, *qh, *ql, *ah, *al;
    cudaGetSymbolAddress((void**)&xh,  g_xh);
    cudaGetSymbolAddress((void**)&xl,  g_xl);
    cudaGetSymbolAddress((void**)&wqh, g_wqh);
    cudaGetSymbolAddress((void**)&wql, g_wql);
    cudaGetSymbolAddress((void**)&woh, g_woh);
    cudaGetSymbolAddress((void**)&wol, g_wol);
    cudaGetSymbolAddress((void**)&qh,  g_qh);
    cudaGetSymbolAddress((void**)&ql,  g_ql);
    cudaGetSymbolAddress((void**)&ah,  g_ah);
    cudaGetSymbolAddress((void**)&al,  g_al);

    cudaFuncSetAttribute(gemm_mma<true>,
                         cudaFuncAttributeMaxDynamicSharedMemorySize, GEMM_SMEM);
    cudaFuncSetAttribute(gemm_mma<false>,
                         cudaFuncAttributeMaxDynamicSharedMemorySize, GEMM_SMEM);
    cudaFuncSetAttribute(attn_mma,
                         cudaFuncAttributeMaxDynamicSharedMemorySize, ATT_SMEM);

    // 0) split inputs to fp16 two-digit
    split_f16<<<512, 256>>>(x,    xh,  xl,  M_TOT * D_);
    split_f16<<<512, 256>>>(Wqkv, wqh, wql, QKV_N * D_);
    split_f16<<<256, 256>>>(Wout, woh, wol, D_ * D_);

    // 1) qkv = x @ Wqkv^T  -> fp16 two-digit
    gemm_mma<true><<<dim3(QKV_N / 128, M_TOT / 128), 256, GEMM_SMEM>>>(
        xh, xl, wqh, wql, nullptr, qh, ql, QKV_N);

    // 2) attention -> g_ah/g_al
    attn_mma<<<dim3(S_ / 128, B_ * H_), 256, ATT_SMEM>>>();

    // 3) out = attn @ Wout^T -> fp32
    gemm_mma<false><<<dim3(D_ / 128, M_TOT / 128), 256, GEMM_SMEM>>>(
        ah, al, woh, wol, out, nullptr, nullptr, D_);
}

// round 10
// speedup vs baseline: 2.3568x; 1.4896x over previous
#include <cuda_runtime.h>
#include <cuda_fp16.h>
#include <math.h>
#include <stdint.h>

// ---------------------------------------------------------------------------
// Problem constants
// ---------------------------------------------------------------------------
#define B_    2
#define S_    2048
#define D_    1024
#define H_    16
#define DH_   64
#define M_TOT (B_ * S_)      // 4096
#define QKV_N (3 * D_)       // 3072
#define K_    1024
#define SCALE 0.125f

// ---------------------------------------------------------------------------
// Scratch: fp16 two-digit (v = h + l, l = fp16 residual, unscaled)
// ---------------------------------------------------------------------------
__device__ __half g_xh[M_TOT * D_],  g_xl[M_TOT * D_];
__device__ __half g_wqh[QKV_N * D_], g_wql[QKV_N * D_];   // lo unused (B-side)
__device__ __half g_woh[D_ * D_],    g_wol[D_ * D_];      // lo unused (B-side)
__device__ __half g_qh[M_TOT * QKV_N], g_ql[M_TOT * QKV_N];
__device__ __half g_ah[M_TOT * D_],  g_al[M_TOT * D_];

// ---------------------------------------------------------------------------
// Helpers
// ---------------------------------------------------------------------------
__device__ __forceinline__ uint32_t sptr(const void* p) {
    return (uint32_t)__cvta_generic_to_shared(p);
}
__device__ __forceinline__ void cp16(uint32_t d, const void* s) {
    asm volatile("cp.async.cg.shared.global [%0], [%1], 16;" :: "r"(d), "l"(s));
}
#define CP_COMMIT() asm volatile("cp.async.commit_group;" ::: "memory")
#define CP_WAIT(n)  asm volatile("cp.async.wait_group %0;" :: "n"(n) : "memory")

__device__ __forceinline__ uint32_t sw128(uint32_t o) {   // Swizzle<3,4,3>
    return o ^ ((o >> 3) & 0x70);
}
__device__ __forceinline__ void ldsm4(uint32_t a, uint32_t r[4]) {
    asm volatile("ldmatrix.sync.aligned.m8n8.x4.shared.b16 {%0,%1,%2,%3}, [%4];"
                 : "=r"(r[0]), "=r"(r[1]), "=r"(r[2]), "=r"(r[3]) : "r"(a));
}
__device__ __forceinline__ void ldsm4t(uint32_t a, uint32_t r[4]) {
    asm volatile("ldmatrix.sync.aligned.m8n8.x4.trans.shared.b16 {%0,%1,%2,%3}, [%4];"
                 : "=r"(r[0]), "=r"(r[1]), "=r"(r[2]), "=r"(r[3]) : "r"(a));
}
__device__ __forceinline__ void mma_f16(float c[4], const uint32_t a[4],
                                        uint32_t b0, uint32_t b1) {
    asm volatile(
        "mma.sync.aligned.m16n8k16.row.col.f32.f16.f16.f32 "
        "{%0,%1,%2,%3}, {%4,%5,%6,%7}, {%8,%9}, {%0,%1,%2,%3};"
        : "+f"(c[0]), "+f"(c[1]), "+f"(c[2]), "+f"(c[3])
        : "r"(a[0]), "r"(a[1]), "r"(a[2]), "r"(a[3]), "r"(b0), "r"(b1));
}
// pack (a,b) -> fp16x2 hi + fp16x2 residual
__device__ __forceinline__ void split_pack(float a, float b, uint32_t& hi, uint32_t& lo) {
    __half2 hp = __floats2half2_rn(a, b);
    float ra = a - __half2float(__low2half(hp));
    float rb = b - __half2float(__high2half(hp));
    __half2 lp = __floats2half2_rn(ra, rb);
    hi = *(uint32_t*)&hp;
    lo = *(uint32_t*)&lp;
}

// ---------------------------------------------------------------------------
// Split: fp32 -> fp16 hi + fp16 residual
// ---------------------------------------------------------------------------
__global__ void split_f16(const float* __restrict__ src,
                          __half* __restrict__ hi, __half* __restrict__ lo, int n)
{
    for (int i = blockIdx.x * blockDim.x + threadIdx.x; i < n; i += gridDim.x * blockDim.x) {
        float v = src[i];
        __half h = __float2half_rn(v);
        hi[i] = h;
        lo[i] = __float2half_rn(v - __half2float(h));
    }
}

// ---------------------------------------------------------------------------
// GEMM: C[M,N] = A[M,1024] @ B[N,1024]^T; A split (hi+lo), B single fp16.
// acc += Ah*B ; acc += Al*B  (2-pass, one f32 accumulator).
// CTA 128x256, 8 warps (2x4, warp tile 64x64), BK=32, 3-stage cp.async.
// ---------------------------------------------------------------------------
#define PKB 80
#define ASZ (128 * PKB)                 // 10240
#define BSZ (256 * PKB)                 // 20480
#define GSTAGE (2 * ASZ + BSZ)          // 40960 (Ah|Al|B)
#define GEMM_SMEM (3 * GSTAGE)          // 122880
#define NCHUNK 32

template<bool SPLIT>
__global__ __launch_bounds__(256) void gemm_mma(
    const __half* __restrict__ Ah, const __half* __restrict__ Al,
    const __half* __restrict__ Bs,
    float* __restrict__ Cf, __half* __restrict__ Chi, __half* __restrict__ Clo, int N)
{
    extern __shared__ char smx[];
    const int tid = threadIdx.x, lane = tid & 31, wid = tid >> 5;
    const int bm = blockIdx.y * 128, bn = blockIdx.x * 256;
    const int m0 = (wid >> 2) * 64, n0 = (wid & 3) * 64;

    const __half* pAh = Ah + (size_t)bm * K_;
    const __half* pAl = Al + (size_t)bm * K_;
    const __half* pB  = Bs + (size_t)bn * K_;

    float acc[4][8][4];
    #pragma unroll
    for (int i = 0; i < 4; i++)
        #pragma unroll
        for (int j = 0; j < 8; j++)
            #pragma unroll
            for (int q = 0; q < 4; q++) acc[i][j][q] = 0.0f;

    auto load_stage = [&](int s, int k0) {
        char* base = smx + s * GSTAGE;
        #pragma unroll
        for (int i = 0; i < 2; i++) {       // A hi + lo: 128 rows x 4 x 16B
            int idx = tid + i * 256;
            int r = idx >> 2, c = idx & 3;
            cp16(sptr(base + r * PKB + c * 16),       pAh + (size_t)r * K_ + k0 + c * 8);
            cp16(sptr(base + ASZ + r * PKB + c * 16), pAl + (size_t)r * K_ + k0 + c * 8);
        }
        #pragma unroll
        for (int i = 0; i < 4; i++) {       // B: 256 rows x 4 x 16B
            int idx = tid + i * 256;
            int r = idx >> 2, c = idx & 3;
            cp16(sptr(base + 2 * ASZ + r * PKB + c * 16),
                 pB + (size_t)r * K_ + k0 + c * 8);
        }
    };

    load_stage(0, 0);  CP_COMMIT();
    load_stage(1, 32); CP_COMMIT();

    const int row_in = lane & 7, g = lane >> 3;

    for (int kc = 0; kc < NCHUNK; kc++) {
        if (kc == NCHUNK - 1) { CP_WAIT(0); } else { CP_WAIT(1); }
        __syncthreads();
        if (kc + 2 < NCHUNK) {
            load_stage((kc + 2) % 3, (kc + 2) * 32);
            CP_COMMIT();
        }

        char* base = smx + (kc % 3) * GSTAGE;
        uint32_t bAh = sptr(base), bAl = bAh + ASZ, bB = bAh + 2 * ASZ;

        #pragma unroll
        for (int ks = 0; ks < 2; ks++) {
            uint32_t ahf[4][4], alf[4][4];
            #pragma unroll
            for (int mt = 0; mt < 4; mt++) {
                uint32_t off = (uint32_t)(m0 + mt * 16 + row_in + (g & 1) * 8) * PKB
                             + (ks * 16 + (g >> 1) * 8) * 2;
                ldsm4(bAh + off, ahf[mt]);
                ldsm4(bAl + off, alf[mt]);
            }
            #pragma unroll
            for (int gb = 0; gb < 4; gb++) {
                uint32_t bf[4];
                uint32_t off = (uint32_t)(n0 + gb * 16 + ((g >> 1) & 1) * 8 + row_in) * PKB
                             + (ks * 16 + (g & 1) * 8) * 2;
                ldsm4(bB + off, bf);
                #pragma unroll
                for (int mt = 0; mt < 4; mt++)
                    #pragma unroll
                    for (int hf = 0; hf < 2; hf++) {
                        int nt = gb * 2 + hf, ix = hf * 2;
                        mma_f16(acc[mt][nt], ahf[mt], bf[ix], bf[ix + 1]);
                        mma_f16(acc[mt][nt], alf[mt], bf[ix], bf[ix + 1]);
                    }
            }
        }
    }

    #pragma unroll
    for (int mt = 0; mt < 4; mt++)
        #pragma unroll
        for (int nt = 0; nt < 8; nt++) {
            int row = bm + m0 + mt * 16 + (lane >> 2);
            int col = bn + n0 + nt * 8 + (lane & 3) * 2;
            float* c = acc[mt][nt];
            if (SPLIT) {
                uint32_t h0, l0, h1, l1;
                split_pack(c[0], c[1], h0, l0);
                split_pack(c[2], c[3], h1, l1);
                *(uint32_t*)(Chi + (size_t)row * N + col) = h0;
                *(uint32_t*)(Clo + (size_t)row * N + col) = l0;
                *(uint32_t*)(Chi + (size_t)(row + 8) * N + col) = h1;
                *(uint32_t*)(Clo + (size_t)(row + 8) * N + col) = l1;
            } else {
                *(float2*)(Cf + (size_t)row * N + col) = make_float2(c[0], c[1]);
                *(float2*)(Cf + (size_t)(row + 8) * N + col) = make_float2(c[2], c[3]);
            }
        }
}

// ---------------------------------------------------------------------------
// Flash attention: Q split (hi+lo), K/V single fp16; P split, 2-pass mma.
// 8 warps, 128-q tile, double-buffered K/V, SW128 smem 64 KB -> 2 CTAs/SM.
// ---------------------------------------------------------------------------
#define SQH 0
#define SQL 16384
#define SKV0 32768
#define KVSTAGE 16384            // K 8192 | V 8192
#define ATT_SMEM (SKV0 + 2 * KVSTAGE)   // 65536

__global__ __launch_bounds__(256, 2) void attn_mma()
{
    extern __shared__ char smx[];
    const int tid = threadIdx.x, lane = tid & 31, warp = tid >> 5;
    const int qt = blockIdx.x;
    const int b  = blockIdx.y >> 4;
    const int h  = blockIdx.y & 15;
    const int qrow0 = b * S_ + qt * 128;

    const __half* qh = g_qh + (size_t)qrow0 * QKV_N + h * DH_;
    const __half* ql = g_ql + (size_t)qrow0 * QKV_N + h * DH_;
    const __half* kh = g_qh + (size_t)(b * S_) * QKV_N + D_ + h * DH_;
    const __half* vh = g_qh + (size_t)(b * S_) * QKV_N + 2 * D_ + h * DH_;

    uint32_t sb = sptr(smx);

    #pragma unroll
    for (int i = 0; i < 4; i++) {
        int idx = tid + i * 256;
        int r = idx >> 3, c = idx & 7;
        uint32_t so = sw128((uint32_t)(r * 128 + c * 16));
        cp16(sb + SQH + so, qh + (size_t)r * QKV_N + c * 8);
        cp16(sb + SQL + so, ql + (size_t)r * QKV_N + c * 8);
    }
    CP_COMMIT();

    auto ld_kv = [&](int s, int krow) {
        uint32_t base = sb + SKV0 + s * KVSTAGE;
        #pragma unroll
        for (int i = 0; i < 2; i++) {
            int idx = tid + i * 256;
            int r = idx >> 3, c = idx & 7;
            size_t go = (size_t)(krow + r) * QKV_N + c * 8;
            uint32_t so = sw128((uint32_t)(r * 128 + c * 16));
            cp16(base + so,        kh + go);
            cp16(base + 8192 + so, vh + go);
        }
    };

    ld_kv(0, 0);
    CP_COMMIT();
    CP_WAIT(1);
    __syncthreads();

    const int row_in = lane & 7, g = lane >> 3;

    uint32_t qa_h[4][4], qa_l[4][4];
    #pragma unroll
    for (int ks = 0; ks < 4; ks++) {
        uint32_t off = sw128((uint32_t)(warp * 16 + row_in + (g & 1) * 8) * 128
                             + (ks * 16 + (g >> 1) * 8) * 2);
        ldsm4(sb + SQH + off, qa_h[ks]);
        ldsm4(sb + SQL + off, qa_l[ks]);
    }

    float m0 = -1e30f, m1 = -1e30f, l0 = 0.0f, l1 = 0.0f;
    float O[8][4];
    #pragma unroll
    for (int nt = 0; nt < 8; nt++)
        #pragma unroll
        for (int q = 0; q < 4; q++) O[nt][q] = 0.0f;

    for (int kt = 0; kt < S_ / 64; kt++) {
        if (kt + 1 < S_ / 64) {
            ld_kv((kt + 1) & 1, (kt + 1) * 64);
            CP_COMMIT();
            CP_WAIT(1);
        } else {
            CP_WAIT(0);
        }
        __syncthreads();

        uint32_t kvb = sb + SKV0 + (kt & 1) * KVSTAGE;

        // ---- S = (Qh + Ql) @ K^T ----
        float s[8][4];
        #pragma unroll
        for (int nt = 0; nt < 8; nt++)
            #pragma unroll
            for (int q = 0; q < 4; q++) s[nt][q] = 0.0f;

        #pragma unroll
        for (int ks = 0; ks < 4; ks++) {
            #pragma unroll
            for (int gb = 0; gb < 4; gb++) {
                uint32_t bf[4];
                uint32_t off = sw128((uint32_t)(gb * 16 + ((g >> 1) & 1) * 8 + row_in) * 128
                                     + (ks * 16 + (g & 1) * 8) * 2);
                ldsm4(kvb + off, bf);
                #pragma unroll
                for (int hf = 0; hf < 2; hf++) {
                    int nt = gb * 2 + hf, ix = hf * 2;
                    mma_f16(s[nt], qa_h[ks], bf[ix], bf[ix + 1]);
                    mma_f16(s[nt], qa_l[ks], bf[ix], bf[ix + 1]);
                }
            }
        }

        // ---- online softmax ----
        float mx0 = -1e30f, mx1 = -1e30f;
        #pragma unroll
        for (int nt = 0; nt < 8; nt++) {
            #pragma unroll
            for (int q = 0; q < 4; q++) s[nt][q] *= SCALE;
            mx0 = fmaxf(mx0, fmaxf(s[nt][0], s[nt][1]));
            mx1 = fmaxf(mx1, fmaxf(s[nt][2], s[nt][3]));
        }
        mx0 = fmaxf(mx0, __shfl_xor_sync(0xffffffffu, mx0, 1));
        mx0 = fmaxf(mx0, __shfl_xor_sync(0xffffffffu, mx0, 2));
        mx1 = fmaxf(mx1, __shfl_xor_sync(0xffffffffu, mx1, 1));
        mx1 = fmaxf(mx1, __shfl_xor_sync(0xffffffffu, mx1, 2));

        float mn0 = fmaxf(m0, mx0), mn1 = fmaxf(m1, mx1);
        float c0 = __expf(m0 - mn0), c1 = __expf(m1 - mn1);
        float sum0 = 0.0f, sum1 = 0.0f;
        #pragma unroll
        for (int nt = 0; nt < 8; nt++) {
            s[nt][0] = __expf(s[nt][0] - mn0); sum0 += s[nt][0];
            s[nt][1] = __expf(s[nt][1] - mn0); sum0 += s[nt][1];
            s[nt][2] = __expf(s[nt][2] - mn1); sum1 += s[nt][2];
            s[nt][3] = __expf(s[nt][3] - mn1); sum1 += s[nt][3];
        }
        sum0 += __shfl_xor_sync(0xffffffffu, sum0, 1);
        sum0 += __shfl_xor_sync(0xffffffffu, sum0, 2);
        sum1 += __shfl_xor_sync(0xffffffffu, sum1, 1);
        sum1 += __shfl_xor_sync(0xffffffffu, sum1, 2);
        l0 = l0 * c0 + sum0;
        l1 = l1 * c1 + sum1;
        m0 = mn0; m1 = mn1;
        #pragma unroll
        for (int nt = 0; nt < 8; nt++) {
            O[nt][0] *= c0; O[nt][1] *= c0;
            O[nt][2] *= c1; O[nt][3] *= c1;
        }

        // ---- O += (Ph + Pl) @ V ----
        #pragma unroll
        for (int j = 0; j < 4; j++) {
            uint32_t pah[4], pal[4];
            split_pack(s[2 * j][0],     s[2 * j][1],     pah[0], pal[0]);
            split_pack(s[2 * j][2],     s[2 * j][3],     pah[1], pal[1]);
            split_pack(s[2 * j + 1][0], s[2 * j + 1][1], pah[2], pal[2]);
            split_pack(s[2 * j + 1][2], s[2 * j + 1][3], pah[3], pal[3]);

            #pragma unroll
            for (int gv = 0; gv < 4; gv++) {
                uint32_t vf[4];
                uint32_t off = sw128((uint32_t)(j * 16 + (g & 1) * 8 + row_in) * 128
                                     + (gv * 16 + (g >> 1) * 8) * 2);
                ldsm4t(kvb + 8192 + off, vf);
                #pragma unroll
                for (int hf = 0; hf < 2; hf++) {
                    int nt = gv * 2 + hf, ix = hf * 2;
                    mma_f16(O[nt], pah, vf[ix], vf[ix + 1]);
                    mma_f16(O[nt], pal, vf[ix], vf[ix + 1]);
                }
            }
        }
        __syncthreads();
    }

    // ---- epilogue: normalize, split for GEMM2 ----
    float inv0 = 1.0f / (l0 + 1e-6f);
    float inv1 = 1.0f / (l1 + 1e-6f);
    int r0g = qrow0 + warp * 16 + (lane >> 2);
    #pragma unroll
    for (int nt = 0; nt < 8; nt++) {
        int col = h * DH_ + nt * 8 + (lane & 3) * 2;
        uint32_t h0, lo0, h1, lo1;
        split_pack(O[nt][0] * inv0, O[nt][1] * inv0, h0, lo0);
        split_pack(O[nt][2] * inv1, O[nt][3] * inv1, h1, lo1);
        *(uint32_t*)(g_ah + (size_t)r0g * D_ + col) = h0;
        *(uint32_t*)(g_al + (size_t)r0g * D_ + col) = lo0;
        *(uint32_t*)(g_ah + (size_t)(r0g + 8) * D_ + col) = h1;
        *(uint32_t*)(g_al + (size_t)(r0g + 8) * D_ + col) = lo1;
    }
}

// ---------------------------------------------------------------------------
// Launch
// ---------------------------------------------------------------------------
extern "C" void kernel_launch(void* const* d_in, const int* in_sizes, int n_in,
                              void* d_out, int out_size)
{
    const float* x    = (const float*)d_in[0];
    const float* Wqkv = (const float*)d_in[1];
    const float* Wout = (const float*)d_in[2];
    float* out = (float*)d_out;

    __half *xh, *xl, *wqh, *wql, *woh, *wol, *qh, *ql, *ah, *al;
    cudaGetSymbolAddress((void**)&xh,  g_xh);
    cudaGetSymbolAddress((void**)&xl,  g_xl);
    cudaGetSymbolAddress((void**)&wqh, g_wqh);
    cudaGetSymbolAddress((void**)&wql, g_wql);
    cudaGetSymbolAddress((void**)&woh, g_woh);
    cudaGetSymbolAddress((void**)&wol, g_wol);
    cudaGetSymbolAddress((void**)&qh,  g_qh);
    cudaGetSymbolAddress((void**)&ql,  g_ql);
    cudaGetSymbolAddress((void**)&ah,  g_ah);
    cudaGetSymbolAddress((void**)&al,  g_al);

    cudaFuncSetAttribute(gemm_mma<true>,
                         cudaFuncAttributeMaxDynamicSharedMemorySize, GEMM_SMEM);
    cudaFuncSetAttribute(gemm_mma<false>,
                         cudaFuncAttributeMaxDynamicSharedMemorySize, GEMM_SMEM);
    cudaFuncSetAttribute(attn_mma,
                         cudaFuncAttributeMaxDynamicSharedMemorySize, ATT_SMEM);

    // 0) split inputs (weights' lo digits unused — B-side is single fp16)
    split_f16<<<512, 256>>>(x,    xh,  xl,  M_TOT * D_);
    split_f16<<<512, 256>>>(Wqkv, wqh, wql, QKV_N * D_);
    split_f16<<<256, 256>>>(Wout, woh, wol, D_ * D_);

    // 1) qkv = x @ Wqkv^T  -> fp16 two-digit
    gemm_mma<true><<<dim3(QKV_N / 256, M_TOT / 128), 256, GEMM_SMEM>>>(
        xh, xl, wqh, nullptr, qh, ql, QKV_N);

    // 2) attention -> g_ah/g_al
    attn_mma<<<dim3(S_ / 128, B_ * H_), 256, ATT_SMEM>>>();

    // 3) out = attn @ Wout^T -> fp32
    gemm_mma<false><<<dim3(D_ / 256, M_TOT / 128), 256, GEMM_SMEM>>>(
        ah, al, woh, out, nullptr, nullptr, D_);
}

// round 11
// speedup vs baseline: 3.8458x; 1.6318x over previous
#include <cuda_runtime.h>
#include <cuda_fp16.h>
#include <math.h>
#include <stdint.h>

// ---------------------------------------------------------------------------
// Problem constants
// ---------------------------------------------------------------------------
#define B_    2
#define S_    2048
#define D_    1024
#define H_    16
#define DH_   64
#define M_TOT (B_ * S_)      // 4096
#define QKV_N (3 * D_)       // 3072
#define K_    1024
#define SCALE 0.125f

// ---------------------------------------------------------------------------
// Scratch: single fp16 everywhere
// ---------------------------------------------------------------------------
__device__ __half g_xh[M_TOT * D_];
__device__ __half g_wqh[QKV_N * D_];
__device__ __half g_woh[D_ * D_];
__device__ __half g_qkv[M_TOT * QKV_N];
__device__ __half g_att[M_TOT * D_];

// ---------------------------------------------------------------------------
// Helpers
// ---------------------------------------------------------------------------
__device__ __forceinline__ uint32_t sptr(const void* p) {
    return (uint32_t)__cvta_generic_to_shared(p);
}
__device__ __forceinline__ void cp16(uint32_t d, const void* s) {
    asm volatile("cp.async.cg.shared.global [%0], [%1], 16;" :: "r"(d), "l"(s));
}
#define CP_COMMIT() asm volatile("cp.async.commit_group;" ::: "memory")
#define CP_WAIT(n)  asm volatile("cp.async.wait_group %0;" :: "n"(n) : "memory")

__device__ __forceinline__ uint32_t sw128(uint32_t o) {   // Swizzle<3,4,3>
    return o ^ ((o >> 3) & 0x70);
}
__device__ __forceinline__ void ldsm4(uint32_t a, uint32_t r[4]) {
    asm volatile("ldmatrix.sync.aligned.m8n8.x4.shared.b16 {%0,%1,%2,%3}, [%4];"
                 : "=r"(r[0]), "=r"(r[1]), "=r"(r[2]), "=r"(r[3]) : "r"(a));
}
__device__ __forceinline__ void ldsm4t(uint32_t a, uint32_t r[4]) {
    asm volatile("ldmatrix.sync.aligned.m8n8.x4.trans.shared.b16 {%0,%1,%2,%3}, [%4];"
                 : "=r"(r[0]), "=r"(r[1]), "=r"(r[2]), "=r"(r[3]) : "r"(a));
}
__device__ __forceinline__ void mma_f16(float c[4], const uint32_t a[4],
                                        uint32_t b0, uint32_t b1) {
    asm volatile(
        "mma.sync.aligned.m16n8k16.row.col.f32.f16.f16.f32 "
        "{%0,%1,%2,%3}, {%4,%5,%6,%7}, {%8,%9}, {%0,%1,%2,%3};"
        : "+f"(c[0]), "+f"(c[1]), "+f"(c[2]), "+f"(c[3])
        : "r"(a[0]), "r"(a[1]), "r"(a[2]), "r"(a[3]), "r"(b0), "r"(b1));
}
__device__ __forceinline__ uint32_t pack_h2(float a, float b) {
    __half2 hp = __floats2half2_rn(a, b);
    return *(uint32_t*)&hp;
}

// ---------------------------------------------------------------------------
// Convert: fp32 -> fp16
// ---------------------------------------------------------------------------
__global__ void conv_f16(const float* __restrict__ src, __half* __restrict__ dst, int n)
{
    int i = (blockIdx.x * blockDim.x + threadIdx.x) * 4;
    for (; i < n; i += gridDim.x * blockDim.x * 4) {
        float4 v = *(const float4*)(src + i);
        __half2 a = __floats2half2_rn(v.x, v.y);
        __half2 b = __floats2half2_rn(v.z, v.w);
        uint2 o = { *(uint32_t*)&a, *(uint32_t*)&b };
        *(uint2*)(dst + i) = o;
    }
}

// ---------------------------------------------------------------------------
// GEMM: C[M,N] = A[M,1024] @ B[N,1024]^T, single-pass fp16, f32 accum.
// CTA 128x256, 8 warps (2x4, warp tile 64x64), BK=32, 3-stage cp.async.
// ---------------------------------------------------------------------------
#define PKB 80
#define ASZ (128 * PKB)                 // 10240
#define BSZ (256 * PKB)                 // 20480
#define GSTAGE (ASZ + BSZ)              // 30720
#define GEMM_SMEM (3 * GSTAGE)          // 92160
#define NCHUNK 32

template<bool HOUT>
__global__ __launch_bounds__(256) void gemm_mma(
    const __half* __restrict__ As, const __half* __restrict__ Bs,
    float* __restrict__ Cf, __half* __restrict__ Ch, int N)
{
    extern __shared__ char smx[];
    const int tid = threadIdx.x, lane = tid & 31, wid = tid >> 5;
    const int bm = blockIdx.y * 128, bn = blockIdx.x * 256;
    const int m0 = (wid >> 2) * 64, n0 = (wid & 3) * 64;

    const __half* pA = As + (size_t)bm * K_;
    const __half* pB = Bs + (size_t)bn * K_;

    float acc[4][8][4];
    #pragma unroll
    for (int i = 0; i < 4; i++)
        #pragma unroll
        for (int j = 0; j < 8; j++)
            #pragma unroll
            for (int q = 0; q < 4; q++) acc[i][j][q] = 0.0f;

    auto load_stage = [&](int s, int k0) {
        char* base = smx + s * GSTAGE;
        #pragma unroll
        for (int i = 0; i < 2; i++) {       // A: 128 rows x 4 x 16B
            int idx = tid + i * 256;
            int r = idx >> 2, c = idx & 3;
            cp16(sptr(base + r * PKB + c * 16), pA + (size_t)r * K_ + k0 + c * 8);
        }
        #pragma unroll
        for (int i = 0; i < 4; i++) {       // B: 256 rows x 4 x 16B
            int idx = tid + i * 256;
            int r = idx >> 2, c = idx & 3;
            cp16(sptr(base + ASZ + r * PKB + c * 16), pB + (size_t)r * K_ + k0 + c * 8);
        }
    };

    load_stage(0, 0);  CP_COMMIT();
    load_stage(1, 32); CP_COMMIT();

    const int row_in = lane & 7, g = lane >> 3;

    for (int kc = 0; kc < NCHUNK; kc++) {
        if (kc == NCHUNK - 1) { CP_WAIT(0); } else { CP_WAIT(1); }
        __syncthreads();
        if (kc + 2 < NCHUNK) {
            load_stage((kc + 2) % 3, (kc + 2) * 32);
            CP_COMMIT();
        }

        char* base = smx + (kc % 3) * GSTAGE;
        uint32_t bA = sptr(base), bB = bA + ASZ;

        #pragma unroll
        for (int ks = 0; ks < 2; ks++) {
            uint32_t af[4][4];
            #pragma unroll
            for (int mt = 0; mt < 4; mt++) {
                uint32_t off = (uint32_t)(m0 + mt * 16 + row_in + (g & 1) * 8) * PKB
                             + (ks * 16 + (g >> 1) * 8) * 2;
                ldsm4(bA + off, af[mt]);
            }
            #pragma unroll
            for (int gb = 0; gb < 4; gb++) {
                uint32_t bf[4];
                uint32_t off = (uint32_t)(n0 + gb * 16 + ((g >> 1) & 1) * 8 + row_in) * PKB
                             + (ks * 16 + (g & 1) * 8) * 2;
                ldsm4(bB + off, bf);
                #pragma unroll
                for (int mt = 0; mt < 4; mt++)
                    #pragma unroll
                    for (int hf = 0; hf < 2; hf++) {
                        int nt = gb * 2 + hf, ix = hf * 2;
                        mma_f16(acc[mt][nt], af[mt], bf[ix], bf[ix + 1]);
                    }
            }
        }
    }

    #pragma unroll
    for (int mt = 0; mt < 4; mt++)
        #pragma unroll
        for (int nt = 0; nt < 8; nt++) {
            int row = bm + m0 + mt * 16 + (lane >> 2);
            int col = bn + n0 + nt * 8 + (lane & 3) * 2;
            float* c = acc[mt][nt];
            if (HOUT) {
                *(uint32_t*)(Ch + (size_t)row * N + col) = pack_h2(c[0], c[1]);
                *(uint32_t*)(Ch + (size_t)(row + 8) * N + col) = pack_h2(c[2], c[3]);
            } else {
                *(float2*)(Cf + (size_t)row * N + col) = make_float2(c[0], c[1]);
                *(float2*)(Cf + (size_t)(row + 8) * N + col) = make_float2(c[2], c[3]);
            }
        }
}

// ---------------------------------------------------------------------------
// Flash attention: single-pass fp16 QK^T and PV, f32 accum + fp32 softmax.
// 8 warps, 128-q tile, double-buffered K/V, SW128 smem 48 KB.
// ---------------------------------------------------------------------------
#define SQ   0
#define SKV0 16384
#define KVSTAGE 16384            // K 8192 | V 8192
#define ATT_SMEM (SKV0 + 2 * KVSTAGE)   // 49152

__global__ __launch_bounds__(256, 2) void attn_mma()
{
    extern __shared__ char smx[];
    const int tid = threadIdx.x, lane = tid & 31, warp = tid >> 5;
    const int qt = blockIdx.x;
    const int b  = blockIdx.y >> 4;
    const int h  = blockIdx.y & 15;
    const int qrow0 = b * S_ + qt * 128;

    const __half* qp = g_qkv + (size_t)qrow0 * QKV_N + h * DH_;
    const __half* kp = g_qkv + (size_t)(b * S_) * QKV_N + D_ + h * DH_;
    const __half* vp = g_qkv + (size_t)(b * S_) * QKV_N + 2 * D_ + h * DH_;

    uint32_t sb = sptr(smx);

    // Q tile: 128 rows x 128B, SW128
    #pragma unroll
    for (int i = 0; i < 4; i++) {
        int idx = tid + i * 256;
        int r = idx >> 3, c = idx & 7;
        uint32_t so = sw128((uint32_t)(r * 128 + c * 16));
        cp16(sb + SQ + so, qp + (size_t)r * QKV_N + c * 8);
    }
    CP_COMMIT();

    auto ld_kv = [&](int s, int krow) {
        uint32_t base = sb + SKV0 + s * KVSTAGE;
        #pragma unroll
        for (int i = 0; i < 2; i++) {
            int idx = tid + i * 256;
            int r = idx >> 3, c = idx & 7;
            size_t go = (size_t)(krow + r) * QKV_N + c * 8;
            uint32_t so = sw128((uint32_t)(r * 128 + c * 16));
            cp16(base + so,        kp + go);
            cp16(base + 8192 + so, vp + go);
        }
    };

    ld_kv(0, 0);
    CP_COMMIT();
    CP_WAIT(1);
    __syncthreads();

    const int row_in = lane & 7, g = lane >> 3;

    uint32_t qa[4][4];
    #pragma unroll
    for (int ks = 0; ks < 4; ks++) {
        uint32_t off = sw128((uint32_t)(warp * 16 + row_in + (g & 1) * 8) * 128
                             + (ks * 16 + (g >> 1) * 8) * 2);
        ldsm4(sb + SQ + off, qa[ks]);
    }

    float m0 = -1e30f, m1 = -1e30f, l0 = 0.0f, l1 = 0.0f;
    float O[8][4];
    #pragma unroll
    for (int nt = 0; nt < 8; nt++)
        #pragma unroll
        for (int q = 0; q < 4; q++) O[nt][q] = 0.0f;

    for (int kt = 0; kt < S_ / 64; kt++) {
        if (kt + 1 < S_ / 64) {
            ld_kv((kt + 1) & 1, (kt + 1) * 64);
            CP_COMMIT();
            CP_WAIT(1);
        } else {
            CP_WAIT(0);
        }
        __syncthreads();

        uint32_t kvb = sb + SKV0 + (kt & 1) * KVSTAGE;

        // ---- S = Q @ K^T ----
        float s[8][4];
        #pragma unroll
        for (int nt = 0; nt < 8; nt++)
            #pragma unroll
            for (int q = 0; q < 4; q++) s[nt][q] = 0.0f;

        #pragma unroll
        for (int ks = 0; ks < 4; ks++) {
            #pragma unroll
            for (int gb = 0; gb < 4; gb++) {
                uint32_t bf[4];
                uint32_t off = sw128((uint32_t)(gb * 16 + ((g >> 1) & 1) * 8 + row_in) * 128
                                     + (ks * 16 + (g & 1) * 8) * 2);
                ldsm4(kvb + off, bf);
                #pragma unroll
                for (int hf = 0; hf < 2; hf++) {
                    int nt = gb * 2 + hf, ix = hf * 2;
                    mma_f16(s[nt], qa[ks], bf[ix], bf[ix + 1]);
                }
            }
        }

        // ---- online softmax ----
        float mx0 = -1e30f, mx1 = -1e30f;
        #pragma unroll
        for (int nt = 0; nt < 8; nt++) {
            #pragma unroll
            for (int q = 0; q < 4; q++) s[nt][q] *= SCALE;
            mx0 = fmaxf(mx0, fmaxf(s[nt][0], s[nt][1]));
            mx1 = fmaxf(mx1, fmaxf(s[nt][2], s[nt][3]));
        }
        mx0 = fmaxf(mx0, __shfl_xor_sync(0xffffffffu, mx0, 1));
        mx0 = fmaxf(mx0, __shfl_xor_sync(0xffffffffu, mx0, 2));
        mx1 = fmaxf(mx1, __shfl_xor_sync(0xffffffffu, mx1, 1));
        mx1 = fmaxf(mx1, __shfl_xor_sync(0xffffffffu, mx1, 2));

        float mn0 = fmaxf(m0, mx0), mn1 = fmaxf(m1, mx1);
        float c0 = __expf(m0 - mn0), c1 = __expf(m1 - mn1);
        float sum0 = 0.0f, sum1 = 0.0f;
        #pragma unroll
        for (int nt = 0; nt < 8; nt++) {
            s[nt][0] = __expf(s[nt][0] - mn0); sum0 += s[nt][0];
            s[nt][1] = __expf(s[nt][1] - mn0); sum0 += s[nt][1];
            s[nt][2] = __expf(s[nt][2] - mn1); sum1 += s[nt][2];
            s[nt][3] = __expf(s[nt][3] - mn1); sum1 += s[nt][3];
        }
        sum0 += __shfl_xor_sync(0xffffffffu, sum0, 1);
        sum0 += __shfl_xor_sync(0xffffffffu, sum0, 2);
        sum1 += __shfl_xor_sync(0xffffffffu, sum1, 1);
        sum1 += __shfl_xor_sync(0xffffffffu, sum1, 2);
        l0 = l0 * c0 + sum0;
        l1 = l1 * c1 + sum1;
        m0 = mn0; m1 = mn1;
        #pragma unroll
        for (int nt = 0; nt < 8; nt++) {
            O[nt][0] *= c0; O[nt][1] *= c0;
            O[nt][2] *= c1; O[nt][3] *= c1;
        }

        // ---- O += P @ V ----
        #pragma unroll
        for (int j = 0; j < 4; j++) {
            uint32_t pa[4];
            pa[0] = pack_h2(s[2 * j][0],     s[2 * j][1]);
            pa[1] = pack_h2(s[2 * j][2],     s[2 * j][3]);
            pa[2] = pack_h2(s[2 * j + 1][0], s[2 * j + 1][1]);
            pa[3] = pack_h2(s[2 * j + 1][2], s[2 * j + 1][3]);

            #pragma unroll
            for (int gv = 0; gv < 4; gv++) {
                uint32_t vf[4];
                uint32_t off = sw128((uint32_t)(j * 16 + (g & 1) * 8 + row_in) * 128
                                     + (gv * 16 + (g >> 1) * 8) * 2);
                ldsm4t(kvb + 8192 + off, vf);
                #pragma unroll
                for (int hf = 0; hf < 2; hf++) {
                    int nt = gv * 2 + hf, ix = hf * 2;
                    mma_f16(O[nt], pa, vf[ix], vf[ix + 1]);
                }
            }
        }
        __syncthreads();
    }

    // ---- epilogue: normalize, write fp16 ----
    float inv0 = 1.0f / (l0 + 1e-6f);
    float inv1 = 1.0f / (l1 + 1e-6f);
    int r0g = qrow0 + warp * 16 + (lane >> 2);
    #pragma unroll
    for (int nt = 0; nt < 8; nt++) {
        int col = h * DH_ + nt * 8 + (lane & 3) * 2;
        *(uint32_t*)(g_att + (size_t)r0g * D_ + col) =
            pack_h2(O[nt][0] * inv0, O[nt][1] * inv0);
        *(uint32_t*)(g_att + (size_t)(r0g + 8) * D_ + col) =
            pack_h2(O[nt][2] * inv1, O[nt][3] * inv1);
    }
}

// ---------------------------------------------------------------------------
// Launch
// ---------------------------------------------------------------------------
extern "C" void kernel_launch(void* const* d_in, const int* in_sizes, int n_in,
                              void* d_out, int out_size)
{
    const float* x    = (const float*)d_in[0];
    const float* Wqkv = (const float*)d_in[1];
    const float* Wout = (const float*)d_in[2];
    float* out = (float*)d_out;

    __half *xh, *wqh, *woh, *qkv, *att;
    cudaGetSymbolAddress((void**)&xh,  g_xh);
    cudaGetSymbolAddress((void**)&wqh, g_wqh);
    cudaGetSymbolAddress((void**)&woh, g_woh);
    cudaGetSymbolAddress((void**)&qkv, g_qkv);
    cudaGetSymbolAddress((void**)&att, g_att);

    cudaFuncSetAttribute(gemm_mma<true>,
                         cudaFuncAttributeMaxDynamicSharedMemorySize, GEMM_SMEM);
    cudaFuncSetAttribute(gemm_mma<false>,
                         cudaFuncAttributeMaxDynamicSharedMemorySize, GEMM_SMEM);
    cudaFuncSetAttribute(attn_mma,
                         cudaFuncAttributeMaxDynamicSharedMemorySize, ATT_SMEM);

    // 0) convert inputs to fp16
    conv_f16<<<512, 256>>>(x,    xh,  M_TOT * D_);
    conv_f16<<<512, 256>>>(Wqkv, wqh, QKV_N * D_);
    conv_f16<<<256, 256>>>(Wout, woh, D_ * D_);

    // 1) qkv = x @ Wqkv^T -> fp16
    gemm_mma<true><<<dim3(QKV_N / 256, M_TOT / 128), 256, GEMM_SMEM>>>(
        xh, wqh, nullptr, qkv, QKV_N);

    // 2) attention -> g_att (fp16)
    attn_mma<<<dim3(S_ / 128, B_ * H_), 256, ATT_SMEM>>>();

    // 3) out = attn @ Wout^T -> fp32
    gemm_mma<false><<<dim3(D_ / 256, M_TOT / 128), 256, GEMM_SMEM>>>(
        att, woh, out, nullptr, D_);
}

// round 12
// speedup vs baseline: 3.9821x; 1.0354x over previous
#include <cuda_runtime.h>
#include <cuda_fp16.h>
#include <math.h>
#include <stdint.h>

// ---------------------------------------------------------------------------
// Problem constants
// ---------------------------------------------------------------------------
#define B_    2
#define S_    2048
#define D_    1024
#define H_    16
#define DH_   64
#define M_TOT (B_ * S_)      // 4096
#define QKV_N (3 * D_)       // 3072
#define K_    1024
#define SCALE 0.125f

// ---------------------------------------------------------------------------
// Scratch: single fp16 everywhere (q pre-scaled by 1/8 in GEMM1 epilogue)
// ---------------------------------------------------------------------------
__device__ __half g_xh[M_TOT * D_];
__device__ __half g_wqh[QKV_N * D_];
__device__ __half g_woh[D_ * D_];
__device__ __half g_qkv[M_TOT * QKV_N];
__device__ __half g_att[M_TOT * D_];

// ---------------------------------------------------------------------------
// Helpers
// ---------------------------------------------------------------------------
__device__ __forceinline__ uint32_t sptr(const void* p) {
    return (uint32_t)__cvta_generic_to_shared(p);
}
__device__ __forceinline__ void cp16(uint32_t d, const void* s) {
    asm volatile("cp.async.cg.shared.global [%0], [%1], 16;" :: "r"(d), "l"(s));
}
#define CP_COMMIT() asm volatile("cp.async.commit_group;" ::: "memory")
#define CP_WAIT(n)  asm volatile("cp.async.wait_group %0;" :: "n"(n) : "memory")

__device__ __forceinline__ uint32_t sw128(uint32_t o) {   // Swizzle<3,4,3>
    return o ^ ((o >> 3) & 0x70);
}
__device__ __forceinline__ void ldsm4(uint32_t a, uint32_t r[4]) {
    asm volatile("ldmatrix.sync.aligned.m8n8.x4.shared.b16 {%0,%1,%2,%3}, [%4];"
                 : "=r"(r[0]), "=r"(r[1]), "=r"(r[2]), "=r"(r[3]) : "r"(a));
}
__device__ __forceinline__ void ldsm4t(uint32_t a, uint32_t r[4]) {
    asm volatile("ldmatrix.sync.aligned.m8n8.x4.trans.shared.b16 {%0,%1,%2,%3}, [%4];"
                 : "=r"(r[0]), "=r"(r[1]), "=r"(r[2]), "=r"(r[3]) : "r"(a));
}
__device__ __forceinline__ void mma_f16(float c[4], const uint32_t a[4],
                                        uint32_t b0, uint32_t b1) {
    asm volatile(
        "mma.sync.aligned.m16n8k16.row.col.f32.f16.f16.f32 "
        "{%0,%1,%2,%3}, {%4,%5,%6,%7}, {%8,%9}, {%0,%1,%2,%3};"
        : "+f"(c[0]), "+f"(c[1]), "+f"(c[2]), "+f"(c[3])
        : "r"(a[0]), "r"(a[1]), "r"(a[2]), "r"(a[3]), "r"(b0), "r"(b1));
}
__device__ __forceinline__ uint32_t pack_h2(float a, float b) {
    __half2 hp = __floats2half2_rn(a, b);
    return *(uint32_t*)&hp;
}

// ---------------------------------------------------------------------------
// Convert: fp32 -> fp16
// ---------------------------------------------------------------------------
__global__ void conv_f16(const float* __restrict__ src, __half* __restrict__ dst, int n)
{
    int i = (blockIdx.x * blockDim.x + threadIdx.x) * 4;
    for (; i < n; i += gridDim.x * blockDim.x * 4) {
        float4 v = *(const float4*)(src + i);
        __half2 a = __floats2half2_rn(v.x, v.y);
        __half2 b = __floats2half2_rn(v.z, v.w);
        uint2 o = { *(uint32_t*)&a, *(uint32_t*)&b };
        *(uint2*)(dst + i) = o;
    }
}

// ---------------------------------------------------------------------------
// GEMM: C[M,N] = A[M,1024] @ B[N,1024]^T, single-pass fp16, f32 accum.
// CTA 128x128, 8 warps (2x4 grid, warp tile 64x32), BK=32, 2-stage cp.async,
// 2 CTAs/SM (4 warps/SMSP for latency hiding).
// QSCALE: multiply columns < D_ by 1/8 before store (pre-scales Q).
// ---------------------------------------------------------------------------
#define PKB 80
#define TSZ (128 * PKB)                 // 10240
#define GSTAGE (2 * TSZ)                // 20480 (A|B)
#define GEMM_SMEM (2 * GSTAGE)          // 40960
#define NCHUNK 32

template<bool HOUT, bool QSCALE>
__global__ __launch_bounds__(256, 2) void gemm_mma(
    const __half* __restrict__ As, const __half* __restrict__ Bs,
    float* __restrict__ Cf, __half* __restrict__ Ch, int N)
{
    extern __shared__ char smx[];
    const int tid = threadIdx.x, lane = tid & 31, wid = tid >> 5;
    const int bm = blockIdx.y * 128, bn = blockIdx.x * 128;
    const int m0 = (wid >> 2) * 64, n0 = (wid & 3) * 32;

    const __half* pA = As + (size_t)bm * K_;
    const __half* pB = Bs + (size_t)bn * K_;

    float acc[4][4][4];
    #pragma unroll
    for (int i = 0; i < 4; i++)
        #pragma unroll
        for (int j = 0; j < 4; j++)
            #pragma unroll
            for (int q = 0; q < 4; q++) acc[i][j][q] = 0.0f;

    auto load_stage = [&](int s, int k0) {
        char* base = smx + s * GSTAGE;
        #pragma unroll
        for (int i = 0; i < 2; i++) {       // A + B: 128 rows x 4 x 16B each
            int idx = tid + i * 256;
            int r = idx >> 2, c = idx & 3;
            cp16(sptr(base + r * PKB + c * 16),       pA + (size_t)r * K_ + k0 + c * 8);
            cp16(sptr(base + TSZ + r * PKB + c * 16), pB + (size_t)r * K_ + k0 + c * 8);
        }
    };

    load_stage(0, 0);
    CP_COMMIT();

    const int row_in = lane & 7, g = lane >> 3;

    for (int kc = 0; kc < NCHUNK; kc++) {
        if (kc + 1 < NCHUNK) {
            load_stage((kc + 1) & 1, (kc + 1) * 32);
            CP_COMMIT();
            CP_WAIT(1);
        } else {
            CP_WAIT(0);
        }
        __syncthreads();

        char* base = smx + (kc & 1) * GSTAGE;
        uint32_t bA = sptr(base), bB = bA + TSZ;

        #pragma unroll
        for (int ks = 0; ks < 2; ks++) {
            uint32_t af[4][4];
            #pragma unroll
            for (int mt = 0; mt < 4; mt++) {
                uint32_t off = (uint32_t)(m0 + mt * 16 + row_in + (g & 1) * 8) * PKB
                             + (ks * 16 + (g >> 1) * 8) * 2;
                ldsm4(bA + off, af[mt]);
            }
            uint32_t bf[2][4];
            #pragma unroll
            for (int gb = 0; gb < 2; gb++) {
                uint32_t off = (uint32_t)(n0 + gb * 16 + ((g >> 1) & 1) * 8 + row_in) * PKB
                             + (ks * 16 + (g & 1) * 8) * 2;
                ldsm4(bB + off, bf[gb]);
            }
            #pragma unroll
            for (int mt = 0; mt < 4; mt++)
                #pragma unroll
                for (int nt = 0; nt < 4; nt++) {
                    int gb = nt >> 1, ix = (nt & 1) * 2;
                    mma_f16(acc[mt][nt], af[mt], bf[gb][ix], bf[gb][ix + 1]);
                }
        }
        __syncthreads();
    }

    #pragma unroll
    for (int mt = 0; mt < 4; mt++)
        #pragma unroll
        for (int nt = 0; nt < 4; nt++) {
            int row = bm + m0 + mt * 16 + (lane >> 2);
            int col = bn + n0 + nt * 8 + (lane & 3) * 2;
            float* c = acc[mt][nt];
            float sc = (QSCALE && col < D_) ? SCALE : 1.0f;
            if (HOUT) {
                *(uint32_t*)(Ch + (size_t)row * N + col) = pack_h2(c[0] * sc, c[1] * sc);
                *(uint32_t*)(Ch + (size_t)(row + 8) * N + col) = pack_h2(c[2] * sc, c[3] * sc);
            } else {
                *(float2*)(Cf + (size_t)row * N + col) = make_float2(c[0], c[1]);
                *(float2*)(Cf + (size_t)(row + 8) * N + col) = make_float2(c[2], c[3]);
            }
        }
}

// ---------------------------------------------------------------------------
// Flash attention: single-pass fp16 QK^T and PV (Q pre-scaled by 1/8).
// 8 warps, 128-q tile, double-buffered K/V, SW128 smem 48 KB, 2 CTAs/SM.
// O-rescale skipped when running max unchanged (corr == 1 exactly).
// ---------------------------------------------------------------------------
#define SQ   0
#define SKV0 16384
#define KVSTAGE 16384            // K 8192 | V 8192
#define ATT_SMEM (SKV0 + 2 * KVSTAGE)   // 49152

__global__ __launch_bounds__(256, 2) void attn_mma()
{
    extern __shared__ char smx[];
    const int tid = threadIdx.x, lane = tid & 31, warp = tid >> 5;
    const int qt = blockIdx.x;
    const int b  = blockIdx.y >> 4;
    const int h  = blockIdx.y & 15;
    const int qrow0 = b * S_ + qt * 128;

    const __half* qp = g_qkv + (size_t)qrow0 * QKV_N + h * DH_;
    const __half* kp = g_qkv + (size_t)(b * S_) * QKV_N + D_ + h * DH_;
    const __half* vp = g_qkv + (size_t)(b * S_) * QKV_N + 2 * D_ + h * DH_;

    uint32_t sb = sptr(smx);

    // Q tile: 128 rows x 128B, SW128
    #pragma unroll
    for (int i = 0; i < 4; i++) {
        int idx = tid + i * 256;
        int r = idx >> 3, c = idx & 7;
        uint32_t so = sw128((uint32_t)(r * 128 + c * 16));
        cp16(sb + SQ + so, qp + (size_t)r * QKV_N + c * 8);
    }
    CP_COMMIT();

    auto ld_kv = [&](int s, int krow) {
        uint32_t base = sb + SKV0 + s * KVSTAGE;
        #pragma unroll
        for (int i = 0; i < 2; i++) {
            int idx = tid + i * 256;
            int r = idx >> 3, c = idx & 7;
            size_t go = (size_t)(krow + r) * QKV_N + c * 8;
            uint32_t so = sw128((uint32_t)(r * 128 + c * 16));
            cp16(base + so,        kp + go);
            cp16(base + 8192 + so, vp + go);
        }
    };

    ld_kv(0, 0);
    CP_COMMIT();
    CP_WAIT(1);
    __syncthreads();

    const int row_in = lane & 7, g = lane >> 3;

    uint32_t qa[4][4];
    #pragma unroll
    for (int ks = 0; ks < 4; ks++) {
        uint32_t off = sw128((uint32_t)(warp * 16 + row_in + (g & 1) * 8) * 128
                             + (ks * 16 + (g >> 1) * 8) * 2);
        ldsm4(sb + SQ + off, qa[ks]);
    }

    float m0 = -1e30f, m1 = -1e30f, l0 = 0.0f, l1 = 0.0f;
    float O[8][4];
    #pragma unroll
    for (int nt = 0; nt < 8; nt++)
        #pragma unroll
        for (int q = 0; q < 4; q++) O[nt][q] = 0.0f;

    for (int kt = 0; kt < S_ / 64; kt++) {
        if (kt + 1 < S_ / 64) {
            ld_kv((kt + 1) & 1, (kt + 1) * 64);
            CP_COMMIT();
            CP_WAIT(1);
        } else {
            CP_WAIT(0);
        }
        __syncthreads();

        uint32_t kvb = sb + SKV0 + (kt & 1) * KVSTAGE;

        // ---- S = Q @ K^T (already includes 1/8 scale via Q) ----
        float s[8][4];
        #pragma unroll
        for (int nt = 0; nt < 8; nt++)
            #pragma unroll
            for (int q = 0; q < 4; q++) s[nt][q] = 0.0f;

        #pragma unroll
        for (int ks = 0; ks < 4; ks++) {
            #pragma unroll
            for (int gb = 0; gb < 4; gb++) {
                uint32_t bf[4];
                uint32_t off = sw128((uint32_t)(gb * 16 + ((g >> 1) & 1) * 8 + row_in) * 128
                                     + (ks * 16 + (g & 1) * 8) * 2);
                ldsm4(kvb + off, bf);
                #pragma unroll
                for (int hf = 0; hf < 2; hf++) {
                    int nt = gb * 2 + hf, ix = hf * 2;
                    mma_f16(s[nt], qa[ks], bf[ix], bf[ix + 1]);
                }
            }
        }

        // ---- online softmax ----
        float mx0 = -1e30f, mx1 = -1e30f;
        #pragma unroll
        for (int nt = 0; nt < 8; nt++) {
            mx0 = fmaxf(mx0, fmaxf(s[nt][0], s[nt][1]));
            mx1 = fmaxf(mx1, fmaxf(s[nt][2], s[nt][3]));
        }
        mx0 = fmaxf(mx0, __shfl_xor_sync(0xffffffffu, mx0, 1));
        mx0 = fmaxf(mx0, __shfl_xor_sync(0xffffffffu, mx0, 2));
        mx1 = fmaxf(mx1, __shfl_xor_sync(0xffffffffu, mx1, 1));
        mx1 = fmaxf(mx1, __shfl_xor_sync(0xffffffffu, mx1, 2));

        float mn0 = fmaxf(m0, mx0), mn1 = fmaxf(m1, mx1);
        // corr == 1 exactly when the max didn't move
        if (mn0 > m0 || mn1 > m1) {
            float c0 = __expf(m0 - mn0), c1 = __expf(m1 - mn1);
            l0 *= c0; l1 *= c1;
            #pragma unroll
            for (int nt = 0; nt < 8; nt++) {
                O[nt][0] *= c0; O[nt][1] *= c0;
                O[nt][2] *= c1; O[nt][3] *= c1;
            }
            m0 = mn0; m1 = mn1;
        }
        float sum0 = 0.0f, sum1 = 0.0f;
        #pragma unroll
        for (int nt = 0; nt < 8; nt++) {
            s[nt][0] = __expf(s[nt][0] - m0); sum0 += s[nt][0];
            s[nt][1] = __expf(s[nt][1] - m0); sum0 += s[nt][1];
            s[nt][2] = __expf(s[nt][2] - m1); sum1 += s[nt][2];
            s[nt][3] = __expf(s[nt][3] - m1); sum1 += s[nt][3];
        }
        sum0 += __shfl_xor_sync(0xffffffffu, sum0, 1);
        sum0 += __shfl_xor_sync(0xffffffffu, sum0, 2);
        sum1 += __shfl_xor_sync(0xffffffffu, sum1, 1);
        sum1 += __shfl_xor_sync(0xffffffffu, sum1, 2);
        l0 += sum0;
        l1 += sum1;

        // ---- O += P @ V ----
        #pragma unroll
        for (int j = 0; j < 4; j++) {
            uint32_t pa[4];
            pa[0] = pack_h2(s[2 * j][0],     s[2 * j][1]);
            pa[1] = pack_h2(s[2 * j][2],     s[2 * j][3]);
            pa[2] = pack_h2(s[2 * j + 1][0], s[2 * j + 1][1]);
            pa[3] = pack_h2(s[2 * j + 1][2], s[2 * j + 1][3]);

            #pragma unroll
            for (int gv = 0; gv < 4; gv++) {
                uint32_t vf[4];
                uint32_t off = sw128((uint32_t)(j * 16 + (g & 1) * 8 + row_in) * 128
                                     + (gv * 16 + (g >> 1) * 8) * 2);
                ldsm4t(kvb + 8192 + off, vf);
                #pragma unroll
                for (int hf = 0; hf < 2; hf++) {
                    int nt = gv * 2 + hf, ix = hf * 2;
                    mma_f16(O[nt], pa, vf[ix], vf[ix + 1]);
                }
            }
        }
        __syncthreads();
    }

    // ---- epilogue: normalize, write fp16 ----
    float inv0 = 1.0f / (l0 + 1e-6f);
    float inv1 = 1.0f / (l1 + 1e-6f);
    int r0g = qrow0 + warp * 16 + (lane >> 2);
    #pragma unroll
    for (int nt = 0; nt < 8; nt++) {
        int col = h * DH_ + nt * 8 + (lane & 3) * 2;
        *(uint32_t*)(g_att + (size_t)r0g * D_ + col) =
            pack_h2(O[nt][0] * inv0, O[nt][1] * inv0);
        *(uint32_t*)(g_att + (size_t)(r0g + 8) * D_ + col) =
            pack_h2(O[nt][2] * inv1, O[nt][3] * inv1);
    }
}

// ---------------------------------------------------------------------------
// Launch
// ---------------------------------------------------------------------------
extern "C" void kernel_launch(void* const* d_in, const int* in_sizes, int n_in,
                              void* d_out, int out_size)
{
    const float* x    = (const float*)d_in[0];
    const float* Wqkv = (const float*)d_in[1];
    const float* Wout = (const float*)d_in[2];
    float* out = (float*)d_out;

    __half *xh, *wqh, *woh, *qkv, *att;
    cudaGetSymbolAddress((void**)&xh,  g_xh);
    cudaGetSymbolAddress((void**)&wqh, g_wqh);
    cudaGetSymbolAddress((void**)&woh, g_woh);
    cudaGetSymbolAddress((void**)&qkv, g_qkv);
    cudaGetSymbolAddress((void**)&att, g_att);

    cudaFuncSetAttribute((const void*)gemm_mma<true, true>,
                         cudaFuncAttributeMaxDynamicSharedMemorySize, GEMM_SMEM);
    cudaFuncSetAttribute((const void*)gemm_mma<false, false>,
                         cudaFuncAttributeMaxDynamicSharedMemorySize, GEMM_SMEM);
    cudaFuncSetAttribute(attn_mma,
                         cudaFuncAttributeMaxDynamicSharedMemorySize, ATT_SMEM);

    // 0) convert inputs to fp16
    conv_f16<<<512, 256>>>(x,    xh,  M_TOT * D_);
    conv_f16<<<512, 256>>>(Wqkv, wqh, QKV_N * D_);
    conv_f16<<<256, 256>>>(Wout, woh, D_ * D_);

    // 1) qkv = x @ Wqkv^T -> fp16 (q columns pre-scaled by 1/8)
    gemm_mma<true, true><<<dim3(QKV_N / 128, M_TOT / 128), 256, GEMM_SMEM>>>(
        xh, wqh, nullptr, qkv, QKV_N);

    // 2) attention -> g_att (fp16)
    attn_mma<<<dim3(S_ / 128, B_ * H_), 256, ATT_SMEM>>>();

    // 3) out = attn @ Wout^T -> fp32
    gemm_mma<false, false><<<dim3(D_ / 128, M_TOT / 128), 256, GEMM_SMEM>>>(
        att, woh, out, nullptr, D_);
}

// round 13
// speedup vs baseline: 4.7662x; 1.1969x over previous
#include <cuda_runtime.h>
#include <cuda_fp16.h>
#include <math.h>
#include <stdint.h>

// ---------------------------------------------------------------------------
// Problem constants
// ---------------------------------------------------------------------------
#define B_    2
#define S_    2048
#define D_    1024
#define H_    16
#define DH_   64
#define M_TOT (B_ * S_)      // 4096
#define QKV_N (3 * D_)       // 3072
#define K_    1024
#define SCALE 0.125f

// ---------------------------------------------------------------------------
// Scratch: single fp16 (q pre-scaled by 1/8 in GEMM1 epilogue)
// ---------------------------------------------------------------------------
__device__ __half g_xh[M_TOT * D_];
__device__ __half g_wqh[QKV_N * D_];
__device__ __half g_woh[D_ * D_];
__device__ __half g_qkv[M_TOT * QKV_N];
__device__ __half g_att[M_TOT * D_];

// ---------------------------------------------------------------------------
// Helpers
// ---------------------------------------------------------------------------
__device__ __forceinline__ uint32_t sptr(const void* p) {
    return (uint32_t)__cvta_generic_to_shared(p);
}
__device__ __forceinline__ void cp16(uint32_t d, const void* s) {
    asm volatile("cp.async.cg.shared.global [%0], [%1], 16;" :: "r"(d), "l"(s));
}
#define CP_COMMIT() asm volatile("cp.async.commit_group;" ::: "memory")
#define CP_WAIT(n)  asm volatile("cp.async.wait_group %0;" :: "n"(n) : "memory")

__device__ __forceinline__ uint32_t sw128(uint32_t o) {   // Swizzle<3,4,3>
    return o ^ ((o >> 3) & 0x70);
}
__device__ __forceinline__ void ldsm4(uint32_t a, uint32_t r[4]) {
    asm volatile("ldmatrix.sync.aligned.m8n8.x4.shared.b16 {%0,%1,%2,%3}, [%4];"
                 : "=r"(r[0]), "=r"(r[1]), "=r"(r[2]), "=r"(r[3]) : "r"(a));
}
__device__ __forceinline__ void ldsm4t(uint32_t a, uint32_t r[4]) {
    asm volatile("ldmatrix.sync.aligned.m8n8.x4.trans.shared.b16 {%0,%1,%2,%3}, [%4];"
                 : "=r"(r[0]), "=r"(r[1]), "=r"(r[2]), "=r"(r[3]) : "r"(a));
}
__device__ __forceinline__ void mma_f16(float c[4], const uint32_t a[4],
                                        uint32_t b0, uint32_t b1) {
    asm volatile(
        "mma.sync.aligned.m16n8k16.row.col.f32.f16.f16.f32 "
        "{%0,%1,%2,%3}, {%4,%5,%6,%7}, {%8,%9}, {%0,%1,%2,%3};"
        : "+f"(c[0]), "+f"(c[1]), "+f"(c[2]), "+f"(c[3])
        : "r"(a[0]), "r"(a[1]), "r"(a[2]), "r"(a[3]), "r"(b0), "r"(b1));
}
__device__ __forceinline__ uint32_t pack_h2(float a, float b) {
    __half2 hp = __floats2half2_rn(a, b);
    return *(uint32_t*)&hp;
}

// ---------------------------------------------------------------------------
// Convert: fp32 -> fp16
// ---------------------------------------------------------------------------
__global__ void conv_f16(const float* __restrict__ src, __half* __restrict__ dst, int n)
{
    int i = (blockIdx.x * blockDim.x + threadIdx.x) * 4;
    for (; i < n; i += gridDim.x * blockDim.x * 4) {
        float4 v = *(const float4*)(src + i);
        __half2 a = __floats2half2_rn(v.x, v.y);
        __half2 b = __floats2half2_rn(v.z, v.w);
        uint2 o = { *(uint32_t*)&a, *(uint32_t*)&b };
        *(uint2*)(dst + i) = o;
    }
}

// ---------------------------------------------------------------------------
// GEMM: C[M,N] = A[M,1024] @ B[N,1024]^T, single-pass fp16, f32 accum.
// CTA 128x256, 8 warps (2x4, warp tile 64x64), BK=64 (128 mma/warp/barrier),
// 3-stage cp.async, SW128 smem layout (48 KB/stage).
// ---------------------------------------------------------------------------
#define GA 16384                        // A tile bytes (128 x 128B)
#define GB 32768                        // B tile bytes (256 x 128B)
#define GST (GA + GB)                   // 49152
#define GEMM_SMEM (3 * GST)             // 147456
#define NCH 16                          // 1024/64

template<bool HOUT, bool QSCALE>
__global__ __launch_bounds__(256) void gemm_mma(
    const __half* __restrict__ As, const __half* __restrict__ Bs,
    float* __restrict__ Cf, __half* __restrict__ Ch, int N)
{
    extern __shared__ char smx[];
    const int tid = threadIdx.x, lane = tid & 31, wid = tid >> 5;
    const int bm = blockIdx.y * 128, bn = blockIdx.x * 256;
    const int m0 = (wid >> 2) * 64, n0 = (wid & 3) * 64;

    const __half* pA = As + (size_t)bm * K_;
    const __half* pB = Bs + (size_t)bn * K_;

    float acc[4][8][4];
    #pragma unroll
    for (int i = 0; i < 4; i++)
        #pragma unroll
        for (int j = 0; j < 8; j++)
            #pragma unroll
            for (int q = 0; q < 4; q++) acc[i][j][q] = 0.0f;

    auto load_stage = [&](int s, int k0) {
        char* base = smx + s * GST;
        #pragma unroll
        for (int i = 0; i < 4; i++) {       // A: 128 rows x 8 x 16B
            int idx = tid + i * 256;
            int r = idx >> 3, c = idx & 7;
            cp16(sptr(base) + sw128((uint32_t)(r * 128 + c * 16)),
                 pA + (size_t)r * K_ + k0 + c * 8);
        }
        #pragma unroll
        for (int i = 0; i < 8; i++) {       // B: 256 rows x 8 x 16B
            int idx = tid + i * 256;
            int r = idx >> 3, c = idx & 7;
            cp16(sptr(base + GA) + sw128((uint32_t)(r * 128 + c * 16)),
                 pB + (size_t)r * K_ + k0 + c * 8);
        }
    };

    load_stage(0, 0);   CP_COMMIT();
    load_stage(1, 64);  CP_COMMIT();

    const int row_in = lane & 7, g = lane >> 3;

    for (int kc = 0; kc < NCH; kc++) {
        if (kc == NCH - 1) { CP_WAIT(0); } else { CP_WAIT(1); }
        __syncthreads();
        if (kc + 2 < NCH) {
            load_stage((kc + 2) % 3, (kc + 2) * 64);
            CP_COMMIT();
        }

        char* base = smx + (kc % 3) * GST;
        uint32_t bA = sptr(base), bB = bA + GA;

        #pragma unroll
        for (int ks = 0; ks < 4; ks++) {
            uint32_t af[4][4];
            #pragma unroll
            for (int mt = 0; mt < 4; mt++) {
                uint32_t off = sw128((uint32_t)(m0 + mt * 16 + row_in + (g & 1) * 8) * 128
                                     + (ks * 16 + (g >> 1) * 8) * 2);
                ldsm4(bA + off, af[mt]);
            }
            #pragma unroll
            for (int gb = 0; gb < 4; gb++) {
                uint32_t bf[4];
                uint32_t off = sw128((uint32_t)(n0 + gb * 16 + ((g >> 1) & 1) * 8 + row_in) * 128
                                     + (ks * 16 + (g & 1) * 8) * 2);
                ldsm4(bB + off, bf);
                #pragma unroll
                for (int mt = 0; mt < 4; mt++)
                    #pragma unroll
                    for (int hf = 0; hf < 2; hf++) {
                        int nt = gb * 2 + hf, ix = hf * 2;
                        mma_f16(acc[mt][nt], af[mt], bf[ix], bf[ix + 1]);
                    }
            }
        }
    }

    #pragma unroll
    for (int mt = 0; mt < 4; mt++)
        #pragma unroll
        for (int nt = 0; nt < 8; nt++) {
            int row = bm + m0 + mt * 16 + (lane >> 2);
            int col = bn + n0 + nt * 8 + (lane & 3) * 2;
            float* c = acc[mt][nt];
            float sc = (QSCALE && col < D_) ? SCALE : 1.0f;
            if (HOUT) {
                *(uint32_t*)(Ch + (size_t)row * N + col) = pack_h2(c[0] * sc, c[1] * sc);
                *(uint32_t*)(Ch + (size_t)(row + 8) * N + col) = pack_h2(c[2] * sc, c[3] * sc);
            } else {
                *(float2*)(Cf + (size_t)row * N + col) = make_float2(c[0], c[1]);
                *(float2*)(Cf + (size_t)(row + 8) * N + col) = make_float2(c[2], c[3]);
            }
        }
}

// ---------------------------------------------------------------------------
// Flash attention: 4 warps x 32 q-rows (q-tile 128), single-pass fp16
// (Q pre-scaled by 1/8), 64-key tiles double-buffered, SW128 smem 48 KB,
// 128 threads, 2 CTAs/SM. 128 mma/warp per barrier interval.
// ---------------------------------------------------------------------------
#define SQ   0
#define SKV0 16384
#define KVSTAGE 16384            // K 8192 | V 8192
#define ATT_SMEM (SKV0 + 2 * KVSTAGE)   // 49152

__global__ __launch_bounds__(128, 2) void attn_mma()
{
    extern __shared__ char smx[];
    const int tid = threadIdx.x, lane = tid & 31, warp = tid >> 5;   // 4 warps
    const int qt = blockIdx.x;
    const int b  = blockIdx.y >> 4;
    const int h  = blockIdx.y & 15;
    const int qrow0 = b * S_ + qt * 128;

    const __half* qp = g_qkv + (size_t)qrow0 * QKV_N + h * DH_;
    const __half* kp = g_qkv + (size_t)(b * S_) * QKV_N + D_ + h * DH_;
    const __half* vp = g_qkv + (size_t)(b * S_) * QKV_N + 2 * D_ + h * DH_;

    uint32_t sb = sptr(smx);

    // Q tile: 128 rows x 128B, SW128
    #pragma unroll
    for (int i = 0; i < 8; i++) {
        int idx = tid + i * 128;
        int r = idx >> 3, c = idx & 7;
        cp16(sb + SQ + sw128((uint32_t)(r * 128 + c * 16)), qp + (size_t)r * QKV_N + c * 8);
    }
    CP_COMMIT();

    auto ld_kv = [&](int s, int krow) {
        uint32_t base = sb + SKV0 + s * KVSTAGE;
        #pragma unroll
        for (int i = 0; i < 4; i++) {
            int idx = tid + i * 128;
            int r = idx >> 3, c = idx & 7;
            size_t go = (size_t)(krow + r) * QKV_N + c * 8;
            uint32_t so = sw128((uint32_t)(r * 128 + c * 16));
            cp16(base + so,        kp + go);
            cp16(base + 8192 + so, vp + go);
        }
    };

    ld_kv(0, 0);
    CP_COMMIT();
    CP_WAIT(1);
    __syncthreads();

    const int row_in = lane & 7, g = lane >> 3;

    // Q fragments: 2 row-blocks of 16 per warp, 4 k-slices
    uint32_t qa[2][4][4];
    #pragma unroll
    for (int mt = 0; mt < 2; mt++)
        #pragma unroll
        for (int ks = 0; ks < 4; ks++) {
            uint32_t off = sw128((uint32_t)(warp * 32 + mt * 16 + row_in + (g & 1) * 8) * 128
                                 + (ks * 16 + (g >> 1) * 8) * 2);
            ldsm4(sb + SQ + off, qa[mt][ks]);
        }

    float m[4] = {-1e30f, -1e30f, -1e30f, -1e30f};
    float l[4] = {0.0f, 0.0f, 0.0f, 0.0f};
    float O[2][8][4];
    #pragma unroll
    for (int mt = 0; mt < 2; mt++)
        #pragma unroll
        for (int nt = 0; nt < 8; nt++)
            #pragma unroll
            for (int q = 0; q < 4; q++) O[mt][nt][q] = 0.0f;

    for (int kt = 0; kt < S_ / 64; kt++) {
        if (kt + 1 < S_ / 64) {
            ld_kv((kt + 1) & 1, (kt + 1) * 64);
            CP_COMMIT();
            CP_WAIT(1);
        } else {
            CP_WAIT(0);
        }
        __syncthreads();

        uint32_t kvb = sb + SKV0 + (kt & 1) * KVSTAGE;

        // ---- S = Q @ K^T (1/8 scale folded into Q) ----
        float s[2][8][4];
        #pragma unroll
        for (int mt = 0; mt < 2; mt++)
            #pragma unroll
            for (int nt = 0; nt < 8; nt++)
                #pragma unroll
                for (int q = 0; q < 4; q++) s[mt][nt][q] = 0.0f;

        #pragma unroll
        for (int ks = 0; ks < 4; ks++) {
            #pragma unroll
            for (int gb = 0; gb < 4; gb++) {
                uint32_t bf[4];
                uint32_t off = sw128((uint32_t)(gb * 16 + ((g >> 1) & 1) * 8 + row_in) * 128
                                     + (ks * 16 + (g & 1) * 8) * 2);
                ldsm4(kvb + off, bf);
                #pragma unroll
                for (int mt = 0; mt < 2; mt++)
                    #pragma unroll
                    for (int hf = 0; hf < 2; hf++) {
                        int nt = gb * 2 + hf, ix = hf * 2;
                        mma_f16(s[mt][nt], qa[mt][ks], bf[ix], bf[ix + 1]);
                    }
            }
        }

        // ---- online softmax (per 16-row block) ----
        #pragma unroll
        for (int mt = 0; mt < 2; mt++) {
            float mx0 = -1e30f, mx1 = -1e30f;
            #pragma unroll
            for (int nt = 0; nt < 8; nt++) {
                mx0 = fmaxf(mx0, fmaxf(s[mt][nt][0], s[mt][nt][1]));
                mx1 = fmaxf(mx1, fmaxf(s[mt][nt][2], s[mt][nt][3]));
            }
            mx0 = fmaxf(mx0, __shfl_xor_sync(0xffffffffu, mx0, 1));
            mx0 = fmaxf(mx0, __shfl_xor_sync(0xffffffffu, mx0, 2));
            mx1 = fmaxf(mx1, __shfl_xor_sync(0xffffffffu, mx1, 1));
            mx1 = fmaxf(mx1, __shfl_xor_sync(0xffffffffu, mx1, 2));

            float mn0 = fmaxf(m[2 * mt], mx0), mn1 = fmaxf(m[2 * mt + 1], mx1);
            if (mn0 > m[2 * mt] || mn1 > m[2 * mt + 1]) {
                float c0 = __expf(m[2 * mt] - mn0), c1 = __expf(m[2 * mt + 1] - mn1);
                l[2 * mt] *= c0; l[2 * mt + 1] *= c1;
                #pragma unroll
                for (int nt = 0; nt < 8; nt++) {
                    O[mt][nt][0] *= c0; O[mt][nt][1] *= c0;
                    O[mt][nt][2] *= c1; O[mt][nt][3] *= c1;
                }
                m[2 * mt] = mn0; m[2 * mt + 1] = mn1;
            }
            float sum0 = 0.0f, sum1 = 0.0f;
            #pragma unroll
            for (int nt = 0; nt < 8; nt++) {
                s[mt][nt][0] = __expf(s[mt][nt][0] - m[2 * mt]);     sum0 += s[mt][nt][0];
                s[mt][nt][1] = __expf(s[mt][nt][1] - m[2 * mt]);     sum0 += s[mt][nt][1];
                s[mt][nt][2] = __expf(s[mt][nt][2] - m[2 * mt + 1]); sum1 += s[mt][nt][2];
                s[mt][nt][3] = __expf(s[mt][nt][3] - m[2 * mt + 1]); sum1 += s[mt][nt][3];
            }
            sum0 += __shfl_xor_sync(0xffffffffu, sum0, 1);
            sum0 += __shfl_xor_sync(0xffffffffu, sum0, 2);
            sum1 += __shfl_xor_sync(0xffffffffu, sum1, 1);
            sum1 += __shfl_xor_sync(0xffffffffu, sum1, 2);
            l[2 * mt] += sum0;
            l[2 * mt + 1] += sum1;
        }

        // ---- O += P @ V (V fragments shared across both row blocks) ----
        #pragma unroll
        for (int j = 0; j < 4; j++) {
            uint32_t pa[2][4];
            #pragma unroll
            for (int mt = 0; mt < 2; mt++) {
                pa[mt][0] = pack_h2(s[mt][2 * j][0],     s[mt][2 * j][1]);
                pa[mt][1] = pack_h2(s[mt][2 * j][2],     s[mt][2 * j][3]);
                pa[mt][2] = pack_h2(s[mt][2 * j + 1][0], s[mt][2 * j + 1][1]);
                pa[mt][3] = pack_h2(s[mt][2 * j + 1][2], s[mt][2 * j + 1][3]);
            }
            #pragma unroll
            for (int gv = 0; gv < 4; gv++) {
                uint32_t vf[4];
                uint32_t off = sw128((uint32_t)(j * 16 + (g & 1) * 8 + row_in) * 128
                                     + (gv * 16 + (g >> 1) * 8) * 2);
                ldsm4t(kvb + 8192 + off, vf);
                #pragma unroll
                for (int mt = 0; mt < 2; mt++)
                    #pragma unroll
                    for (int hf = 0; hf < 2; hf++) {
                        int nt = gv * 2 + hf, ix = hf * 2;
                        mma_f16(O[mt][nt], pa[mt], vf[ix], vf[ix + 1]);
                    }
            }
        }
        __syncthreads();
    }

    // ---- epilogue: normalize, write fp16 ----
    #pragma unroll
    for (int mt = 0; mt < 2; mt++) {
        float inv0 = 1.0f / (l[2 * mt] + 1e-6f);
        float inv1 = 1.0f / (l[2 * mt + 1] + 1e-6f);
        int r0g = qrow0 + warp * 32 + mt * 16 + (lane >> 2);
        #pragma unroll
        for (int nt = 0; nt < 8; nt++) {
            int col = h * DH_ + nt * 8 + (lane & 3) * 2;
            *(uint32_t*)(g_att + (size_t)r0g * D_ + col) =
                pack_h2(O[mt][nt][0] * inv0, O[mt][nt][1] * inv0);
            *(uint32_t*)(g_att + (size_t)(r0g + 8) * D_ + col) =
                pack_h2(O[mt][nt][2] * inv1, O[mt][nt][3] * inv1);
        }
    }
}

// ---------------------------------------------------------------------------
// Launch
// ---------------------------------------------------------------------------
extern "C" void kernel_launch(void* const* d_in, const int* in_sizes, int n_in,
                              void* d_out, int out_size)
{
    const float* x    = (const float*)d_in[0];
    const float* Wqkv = (const float*)d_in[1];
    const float* Wout = (const float*)d_in[2];
    float* out = (float*)d_out;

    __half *xh, *wqh, *woh, *qkv, *att;
    cudaGetSymbolAddress((void**)&xh,  g_xh);
    cudaGetSymbolAddress((void**)&wqh, g_wqh);
    cudaGetSymbolAddress((void**)&woh, g_woh);
    cudaGetSymbolAddress((void**)&qkv, g_qkv);
    cudaGetSymbolAddress((void**)&att, g_att);

    cudaFuncSetAttribute((const void*)gemm_mma<true, true>,
                         cudaFuncAttributeMaxDynamicSharedMemorySize, GEMM_SMEM);
    cudaFuncSetAttribute((const void*)gemm_mma<false, false>,
                         cudaFuncAttributeMaxDynamicSharedMemorySize, GEMM_SMEM);
    cudaFuncSetAttribute(attn_mma,
                         cudaFuncAttributeMaxDynamicSharedMemorySize, ATT_SMEM);

    // 0) convert inputs to fp16
    conv_f16<<<512, 256>>>(x,    xh,  M_TOT * D_);
    conv_f16<<<512, 256>>>(Wqkv, wqh, QKV_N * D_);
    conv_f16<<<256, 256>>>(Wout, woh, D_ * D_);

    // 1) qkv = x @ Wqkv^T -> fp16 (q columns pre-scaled by 1/8)
    gemm_mma<true, true><<<dim3(QKV_N / 256, M_TOT / 128), 256, GEMM_SMEM>>>(
        xh, wqh, nullptr, qkv, QKV_N);

    // 2) attention -> g_att (fp16)
    attn_mma<<<dim3(S_ / 128, B_ * H_), 128, ATT_SMEM>>>();

    // 3) out = attn @ Wout^T -> fp32
    gemm_mma<false, false><<<dim3(D_ / 256, M_TOT / 128), 256, GEMM_SMEM>>>(
        att, woh, out, nullptr, D_);
}